// round 5
// baseline (speedup 1.0000x reference)
#include <cuda_runtime.h>
#include <cuda_fp16.h>
#include <cstdint>
#include <cstddef>

// ---------------------------------------------------------------------------
// DecayBlock (Mamba-2 SSD block) — round 5: fp16 mma.sync GEMMs.
//   tcgen05 is unreachable (harness compiles via compute_100, no 'a'), so the
//   legacy tensor path is the ceiling. fp16 m16n8k16 doubles tf32 throughput
//   with IDENTICAL mantissa width (11 bits) -> same rel_err, ~2x GEMM speed.
//   * GEMM1 xi-cols + GEMM2: fp16 mma, fp32 accum, double-buffered smem
//   * GEMM1 w-cols: exact fp32 (exponentiated downstream)
//   * SSD kernels unchanged from R3
// ---------------------------------------------------------------------------

namespace {
constexpr int B_  = 8;
constexpr int S_  = 4096;
constexpr int DM_ = 1024;
constexpr int H_  = 16;
constexpr int N_  = 64;
constexpr int C_  = 64;
constexpr int E_  = 1040;
constexpr int M_  = B_ * S_;
constexpr int SHW = 20;   // smem row stride in words (32 halves + 8 pad)
}

__device__ __align__(16) float g_xw[(size_t)M_ * E_];
__device__ __align__(16) float g_y[(size_t)M_ * DM_];
__device__ __align__(16) float g_states[B_ * H_ * C_ * N_];
__device__ float g_cnorm[B_ * H_ * C_];
__device__ float g_T[B_ * H_ * C_];
__device__ __align__(16) float g_nstates[B_ * H_ * C_ * N_];
__device__ float g_nnorm[B_ * H_ * C_];

__device__ __forceinline__ uint32_t pk(float lo, float hi) {
    __half2 h = __floats2half2_rn(lo, hi);
    return *reinterpret_cast<uint32_t*>(&h);
}

__device__ __forceinline__ void mma_f16(float* c, const uint32_t* a, const uint32_t* b) {
    asm volatile(
        "mma.sync.aligned.m16n8k16.row.col.f32.f16.f16.f32 "
        "{%0,%1,%2,%3}, {%4,%5,%6,%7}, {%8,%9}, {%0,%1,%2,%3};\n"
        : "+f"(c[0]), "+f"(c[1]), "+f"(c[2]), "+f"(c[3])
        : "r"(a[0]), "r"(a[1]), "r"(a[2]), "r"(a[3]), "r"(b[0]), "r"(b[1]));
}

// ---------------------------------------------------------------------------
// FP16 tensor GEMM (NT): C[M,N] = A[M,K] * B[N,K]^T
// 128x128 tile, BK=32, 2-stage smem ring + register prefetch, 256 threads
// (8 warps 2x4), warp tile 64x32, mma m16n8k16, fp32 accum.
// M,N multiples of 128; K multiple of 32.
// ---------------------------------------------------------------------------
template <bool FIRST>
__global__ __launch_bounds__(256)
void hgemm_nt(const float* __restrict__ Aarg, const float* __restrict__ Bw,
              float* __restrict__ Carg, int K, int ldc)
{
    const float* A = FIRST ? Aarg : g_y;
    float*       C = FIRST ? g_xw : Carg;

    __shared__ uint32_t As[2][128 * SHW];
    __shared__ uint32_t Bs[2][128 * SHW];

    const int tid  = threadIdx.x;
    const int lane = tid & 31;
    const int warp = tid >> 5;
    const int wm   = warp & 1;        // m offset wm*64
    const int wn   = warp >> 1;       // n offset wn*32
    const int grp  = lane >> 2;       // 0..7
    const int tig  = lane & 3;        // 0..3

    const int m0 = blockIdx.y * 128;
    const int n0 = blockIdx.x * 128;

    const int lrow = tid >> 1;        // 0..127
    const int lk   = (tid & 1) * 16;  // float offset 0 or 16

    const float* gA = A  + (size_t)(m0 + lrow) * K + lk;
    const float* gB = Bw + (size_t)(n0 + lrow) * K + lk;
    uint32_t* const dA0 = &As[0][lrow * SHW + (tid & 1) * 8];
    uint32_t* const dA1 = &As[1][lrow * SHW + (tid & 1) * 8];
    uint32_t* const dB0 = &Bs[0][lrow * SHW + (tid & 1) * 8];
    uint32_t* const dB1 = &Bs[1][lrow * SHW + (tid & 1) * 8];

    float acc[4][4][4];
#pragma unroll
    for (int i = 0; i < 4; i++)
#pragma unroll
        for (int j = 0; j < 4; j++)
#pragma unroll
            for (int r = 0; r < 4; r++) acc[i][j][r] = 0.f;

    float4 ra[4], rb[4];
    auto load_regs = [&](int k0) {
#pragma unroll
        for (int q = 0; q < 4; q++) {
            ra[q] = *reinterpret_cast<const float4*>(gA + k0 + q * 4);
            rb[q] = *reinterpret_cast<const float4*>(gB + k0 + q * 4);
        }
    };
    auto store_stage = [&](int st) {
        uint32_t* dA = st ? dA1 : dA0;
        uint32_t* dB = st ? dB1 : dB0;
        uint4 ua0 = make_uint4(pk(ra[0].x, ra[0].y), pk(ra[0].z, ra[0].w),
                               pk(ra[1].x, ra[1].y), pk(ra[1].z, ra[1].w));
        uint4 ua1 = make_uint4(pk(ra[2].x, ra[2].y), pk(ra[2].z, ra[2].w),
                               pk(ra[3].x, ra[3].y), pk(ra[3].z, ra[3].w));
        uint4 ub0 = make_uint4(pk(rb[0].x, rb[0].y), pk(rb[0].z, rb[0].w),
                               pk(rb[1].x, rb[1].y), pk(rb[1].z, rb[1].w));
        uint4 ub1 = make_uint4(pk(rb[2].x, rb[2].y), pk(rb[2].z, rb[2].w),
                               pk(rb[3].x, rb[3].y), pk(rb[3].z, rb[3].w));
        *reinterpret_cast<uint4*>(dA)     = ua0;
        *reinterpret_cast<uint4*>(dA + 4) = ua1;
        *reinterpret_cast<uint4*>(dB)     = ub0;
        *reinterpret_cast<uint4*>(dB + 4) = ub1;
    };

    load_regs(0);
    store_stage(0);

    const int NIT = K >> 5;
    for (int it = 0; it < NIT; ++it) {
        __syncthreads();                 // stage (it&1) visible
        const int cur = it & 1;
        if (it + 1 < NIT) load_regs((it + 1) << 5);

        const uint32_t* Ac = As[cur];
        const uint32_t* Bc = Bs[cur];
#pragma unroll
        for (int ks = 0; ks < 2; ks++) {
            const int kw = ks * 8 + tig;
            uint32_t afr[4][4];
#pragma unroll
            for (int mt = 0; mt < 4; mt++) {
                const int m = wm * 64 + mt * 16 + grp;
                afr[mt][0] = Ac[m * SHW + kw];
                afr[mt][1] = Ac[(m + 8) * SHW + kw];
                afr[mt][2] = Ac[m * SHW + kw + 4];
                afr[mt][3] = Ac[(m + 8) * SHW + kw + 4];
            }
            uint32_t bfr[4][2];
#pragma unroll
            for (int nt = 0; nt < 4; nt++) {
                const int n = wn * 32 + nt * 8 + grp;
                bfr[nt][0] = Bc[n * SHW + kw];
                bfr[nt][1] = Bc[n * SHW + kw + 4];
            }
#pragma unroll
            for (int mt = 0; mt < 4; mt++)
#pragma unroll
                for (int nt = 0; nt < 4; nt++)
                    mma_f16(acc[mt][nt], afr[mt], bfr[nt]);
        }
        __syncthreads();                 // all reads of cur done
        if (it + 1 < NIT) store_stage((it + 1) & 1);
    }

#pragma unroll
    for (int mt = 0; mt < 4; mt++) {
        const int row = m0 + wm * 64 + mt * 16 + grp;
#pragma unroll
        for (int nt = 0; nt < 4; nt++) {
            const int col = n0 + wn * 32 + nt * 8 + tig * 2;
            *reinterpret_cast<float2*>(&C[(size_t)row * ldc + col]) =
                make_float2(acc[mt][nt][0], acc[mt][nt][1]);
            *reinterpret_cast<float2*>(&C[(size_t)(row + 8) * ldc + col]) =
                make_float2(acc[mt][nt][2], acc[mt][nt][3]);
        }
    }
}

// ---------------------------------------------------------------------------
// K1b: skinny fp32 GEMM for the 16 "w" columns (exact fp32).
// ---------------------------------------------------------------------------
__global__ __launch_bounds__(256)
void wgemm_kernel(const float* __restrict__ x, const float* __restrict__ ipw)
{
    __shared__ float Xs[128][65];
    __shared__ float Ws[16][64];

    const int tid = threadIdx.x;
    const int col = tid & 15;
    const int rg  = tid >> 4;
    const int m0  = blockIdx.x * 128;

    float acc[8];
#pragma unroll
    for (int r = 0; r < 8; r++) acc[r] = 0.f;

    for (int k0 = 0; k0 < DM_; k0 += 64) {
        {
            const int row = tid >> 1;
            const int kk0 = (tid & 1) * 32;
#pragma unroll
            for (int q = 0; q < 8; q++) {
                float4 v = *reinterpret_cast<const float4*>(
                    &x[(size_t)(m0 + row) * DM_ + k0 + kk0 + q * 4]);
                Xs[row][kk0 + q * 4 + 0] = v.x;
                Xs[row][kk0 + q * 4 + 1] = v.y;
                Xs[row][kk0 + q * 4 + 2] = v.z;
                Xs[row][kk0 + q * 4 + 3] = v.w;
            }
        }
        {
            const int wr = tid >> 4;
            const int wk = (tid & 15) * 4;
            if (wr < 16) {
                float4 v = *reinterpret_cast<const float4*>(
                    &ipw[(size_t)(1024 + wr) * DM_ + k0 + wk]);
                Ws[wr][wk + 0] = v.x;
                Ws[wr][wk + 1] = v.y;
                Ws[wr][wk + 2] = v.z;
                Ws[wr][wk + 3] = v.w;
            }
        }
        __syncthreads();

#pragma unroll 8
        for (int k = 0; k < 64; k++) {
            const float wv = Ws[col][k];
#pragma unroll
            for (int r = 0; r < 8; r++)
                acc[r] = fmaf(Xs[rg + r * 16][k], wv, acc[r]);
        }
        __syncthreads();
    }

#pragma unroll
    for (int r = 0; r < 8; r++)
        g_xw[(size_t)(m0 + rg + r * 16) * E_ + 1024 + col] = acc[r];
}

// ---------------------------------------------------------------------------
// K2: per-(b,h,c) chunk stats — rolling conv window.
// ---------------------------------------------------------------------------
__global__ __launch_bounds__(64)
void chunk_stats_kernel(const float* __restrict__ conv_w,
                        const float* __restrict__ conv_b,
                        const float* __restrict__ w_base)
{
    const int c = blockIdx.x, h = blockIdx.y, b = blockIdx.z;
    const int n = threadIdx.x;

    __shared__ float sS[64];
    __shared__ float sE[64];
    __shared__ float sMin;

    const int ch = h * 64 + n;
    const float cw0 = conv_w[ch * 4 + 0];
    const float cw1 = conv_w[ch * 4 + 1];
    const float cw2 = conv_w[ch * 4 + 2];
    const float cw3 = conv_w[ch * 4 + 3];
    const float cb  = conv_b[ch];

    const int s0 = c * 64;
    const float* xwb = g_xw + (size_t)b * S_ * E_;
    const float* xp  = xwb + (size_t)s0 * E_ + h * 64 + n;

    float xm3 = 0.f, xm2 = 0.f, xm1 = 0.f;
    if (c > 0) {
        xm3 = xp[-(ptrdiff_t)(3 * E_)];
        xm2 = xp[-(ptrdiff_t)(2 * E_)];
        xm1 = xp[-(ptrdiff_t)(1 * E_)];
    }

    sS[n] = xwb[(size_t)(s0 + n) * E_ + 1024 + h] * w_base[h];
    __syncthreads();

    if (n == 0) {
        float run = 0.f, mn = 3.4e38f;
        for (int i = 0; i < 64; i++) {
            run += sS[i];
            sS[i] = run;
            mn = fminf(mn, run);
        }
        sMin = mn;
    }
    __syncthreads();
    sE[n] = __expf(-sS[n]);
    __syncthreads();

    float r = 0.f, rn = 0.f;
#pragma unroll 4
    for (int i = 0; i < 64; i++) {
        const float x0 = xp[(size_t)i * E_];
        const float xv = cb + cw0 * xm3 + cw1 * xm2 + cw2 * xm1 + cw3 * x0;
        xm3 = xm2; xm2 = xm1; xm1 = x0;
        const float e = sE[i];
        r  = fmaf(e, xv, r);
        rn += e;
    }

    const float sc  = __expf(sMin);
    const int   idx = (b * H_ + h) * C_ + c;
    g_states[idx * N_ + n] = sc * r;
    if (n == 0) {
        g_cnorm[idx] = sc * rn;
        g_T[idx]     = sS[63];
    }
}

// ---------------------------------------------------------------------------
// K3: per-(b,h) cross-chunk scan — 256 threads.
// ---------------------------------------------------------------------------
__global__ __launch_bounds__(256)
void chunk_scan_kernel()
{
    const int h = blockIdx.x, b = blockIdx.y;
    const int tid = threadIdx.x;
    const int n  = tid & 63;
    const int zq = tid >> 6;

    __shared__ float G[65];
    __shared__ float MP[64];
    __shared__ float W[64][64];
    __shared__ float st[64][64];
    __shared__ float cn[64];

    const int base = (b * H_ + h) * C_;

    for (int idx = tid; idx < 4096; idx += 256)
        st[idx >> 6][idx & 63] = g_states[(size_t)base * N_ + idx];
    if (tid < 64) cn[tid] = g_cnorm[base + tid];
    __syncthreads();

    if (tid == 0) {
        float run = 0.f;
        G[0] = 0.f;
        for (int c = 0; c < 64; c++) { run += g_T[base + c]; G[c + 1] = run; }
        float mn = 3.4e38f;
        for (int z = 0; z < 64; z++) { mn = fminf(mn, G[z]); MP[z] = mn; }
    }
    __syncthreads();

    for (int idx = tid; idx < 4096; idx += 256) {
        const int z = idx >> 6, cp = idx & 63;
        W[z][cp] = (cp < z) ? __expf(MP[z] - G[cp + 1]) : 0.f;
    }
    __syncthreads();

    for (int z = zq; z < 64; z += 4) {
        float accv = 0.f;
        for (int cp = 0; cp < z; cp++) accv = fmaf(W[z][cp], st[cp][n], accv);
        g_nstates[(base + z) * N_ + n] = accv;
    }
    if (tid < 64) {
        float accn = 0.f;
        for (int cp = 0; cp < tid; cp++) accn = fmaf(W[tid][cp], cn[cp], accn);
        g_nnorm[base + tid] = accn;
    }
}

// ---------------------------------------------------------------------------
// K4: per-(b,h,c) combine -> y — rolling conv window.
// ---------------------------------------------------------------------------
__global__ __launch_bounds__(64)
void combine_kernel(const float* __restrict__ conv_w,
                    const float* __restrict__ conv_b,
                    const float* __restrict__ w_base)
{
    const int c = blockIdx.x, h = blockIdx.y, b = blockIdx.z;
    const int n = threadIdx.x;

    __shared__ float sS[64];
    __shared__ float sE[64], sEMP[64], sSDO[64];
    __shared__ float sMP[64];
    __shared__ float sMax;

    const int ch = h * 64 + n;
    const float cw0 = conv_w[ch * 4 + 0];
    const float cw1 = conv_w[ch * 4 + 1];
    const float cw2 = conv_w[ch * 4 + 2];
    const float cw3 = conv_w[ch * 4 + 3];
    const float cb  = conv_b[ch];

    const int s0 = c * 64;
    const float* xwb = g_xw + (size_t)b * S_ * E_;
    const float* xp  = xwb + (size_t)s0 * E_ + h * 64 + n;

    float xm3 = 0.f, xm2 = 0.f, xm1 = 0.f;
    if (c > 0) {
        xm3 = xp[-(ptrdiff_t)(3 * E_)];
        xm2 = xp[-(ptrdiff_t)(2 * E_)];
        xm1 = xp[-(ptrdiff_t)(1 * E_)];
    }

    sS[n] = xwb[(size_t)(s0 + n) * E_ + 1024 + h] * w_base[h];
    __syncthreads();

    if (n == 0) {
        float run = 0.f, mn = 3.4e38f, mx = -3.4e38f;
        for (int i = 0; i < 64; i++) {
            run += sS[i];
            sS[i] = run;
            mn = fminf(mn, run);
            sMP[i] = mn;
            mx = fmaxf(mx, run);
        }
        sMax = mx;
    }
    __syncthreads();
    sE[n]   = __expf(-sS[n]);
    sEMP[n] = __expf(sMP[n]);
    sSDO[n] = __expf(sS[n] - sMax);
    __syncthreads();

    const int idx = (b * H_ + h) * C_ + c;
    const float ns = g_nstates[idx * N_ + n];
    const float nn = g_nnorm[idx];

    float r = 0.f, rn = 0.f;
    float* yout = g_y + (size_t)(b * S_ + s0) * DM_ + h * 64 + n;

#pragma unroll 4
    for (int i = 0; i < 64; i++) {
        const float x0 = xp[(size_t)i * E_];
        const float xv = cb + cw0 * xm3 + cw1 * xm2 + cw2 * xm1 + cw3 * x0;
        xm3 = xm2; xm2 = xm1; xm1 = x0;
        const float e = sE[i];
        r  = fmaf(e, xv, r);
        rn += e;
        const float emp = sEMP[i];
        const float sdo = sSDO[i];
        const float num = fmaf(sdo, ns, emp * r);
        const float den = fmaf(sdo, nn, emp * rn);
        yout[(size_t)i * DM_] = num / den;
    }
}

// ---------------------------------------------------------------------------
// Launch
// ---------------------------------------------------------------------------
extern "C" void kernel_launch(void* const* d_in, const int* in_sizes, int n_in,
                              void* d_out, int out_size)
{
    const float *x = nullptr, *ipw = nullptr, *cw = nullptr,
                *cb = nullptr, *wb = nullptr, *opw = nullptr;
    for (int i = 0; i < n_in; i++) {
        switch (in_sizes[i]) {
            case M_ * DM_:  x   = (const float*)d_in[i]; break;
            case E_ * DM_:  ipw = (const float*)d_in[i]; break;
            case DM_ * 4:   cw  = (const float*)d_in[i]; break;
            case DM_:       cb  = (const float*)d_in[i]; break;
            case H_:        wb  = (const float*)d_in[i]; break;
            case DM_ * DM_: opw = (const float*)d_in[i]; break;
        }
    }

    // K1a: xi = x @ in_proj_w[:1024]^T (fp16 tensor cores)
    hgemm_nt<true><<<dim3(DM_ / 128, M_ / 128), 256>>>(x, ipw, nullptr, DM_, E_);

    // K1b: w = x @ in_proj_w[1024:]^T (fp32 exact)
    wgemm_kernel<<<M_ / 128, 256>>>(x, ipw);

    // K2: per-chunk stats
    chunk_stats_kernel<<<dim3(C_, H_, B_), 64>>>(cw, cb, wb);

    // K3: cross-chunk scan
    chunk_scan_kernel<<<dim3(H_, B_), 256>>>();

    // K4: combine -> y
    combine_kernel<<<dim3(C_, H_, B_), 64>>>(cw, cb, wb);

    // K5: out = y @ out_proj_w^T (fp16 tensor cores)
    hgemm_nt<false><<<dim3(DM_ / 128, M_ / 128), 256>>>(
        nullptr, opw, (float*)d_out, DM_, DM_);
}

// round 6
// speedup vs baseline: 1.5321x; 1.5321x over previous
#include <cuda_runtime.h>
#include <cuda_fp16.h>
#include <cstdint>
#include <cstddef>

// ---------------------------------------------------------------------------
// DecayBlock (Mamba-2 SSD block) — round 6: fp16 GEMMs done right.
//   R5 lesson: GEMM was LDS-issue-bound (48 scalar LDS vs 32 mma per iter).
//   Fix: pre-convert operands to fp16 in gmem (enables cp.async), use
//   ldmatrix.x4 for fragments (12 LDSM vs 48 LDS), 2-stage async pipeline.
//   * GEMM1 w-cols stays exact fp32 (exponentiated downstream)
//   * SSD kernels unchanged; combine writes y directly as fp16
// ---------------------------------------------------------------------------

namespace {
constexpr int B_  = 8;
constexpr int S_  = 4096;
constexpr int DM_ = 1024;
constexpr int H_  = 16;
constexpr int N_  = 64;
constexpr int C_  = 64;
constexpr int E_  = 1040;
constexpr int M_  = B_ * S_;
constexpr int SHH = 40;                 // smem row stride in halves (32 + 8 pad)
constexpr int STAGE_B = 128 * SHH * 2;  // 10240 bytes per stage per operand
}

// Scratch (allocation-free: __device__ globals)
__device__ __align__(16) float  g_xw[(size_t)M_ * E_];     // in_proj output (fp32)
__device__ __align__(16) __half g_xh[(size_t)M_ * DM_];    // x in fp16
__device__ __align__(16) __half g_yh[(size_t)M_ * DM_];    // ssd output in fp16
__device__ __align__(16) __half g_ipwh[(size_t)DM_ * DM_]; // in_proj_w[:1024] fp16
__device__ __align__(16) __half g_opwh[(size_t)DM_ * DM_]; // out_proj_w fp16
__device__ __align__(16) float g_states[B_ * H_ * C_ * N_];
__device__ float g_cnorm[B_ * H_ * C_];
__device__ float g_T[B_ * H_ * C_];
__device__ __align__(16) float g_nstates[B_ * H_ * C_ * N_];
__device__ float g_nnorm[B_ * H_ * C_];

__device__ __forceinline__ uint32_t pk(float lo, float hi) {
    __half2 h = __floats2half2_rn(lo, hi);
    return *reinterpret_cast<uint32_t*>(&h);
}

__device__ __forceinline__ void mma_f16(float* c, const uint32_t* a, const uint32_t* b) {
    asm volatile(
        "mma.sync.aligned.m16n8k16.row.col.f32.f16.f16.f32 "
        "{%0,%1,%2,%3}, {%4,%5,%6,%7}, {%8,%9}, {%0,%1,%2,%3};\n"
        : "+f"(c[0]), "+f"(c[1]), "+f"(c[2]), "+f"(c[3])
        : "r"(a[0]), "r"(a[1]), "r"(a[2]), "r"(a[3]), "r"(b[0]), "r"(b[1]));
}

__device__ __forceinline__ void cp16(uint32_t smem, const void* gmem) {
    asm volatile("cp.async.cg.shared.global [%0], [%1], 16;\n" :: "r"(smem), "l"(gmem));
}

__device__ __forceinline__ void ldsm4(uint32_t* r, uint32_t addr) {
    asm volatile("ldmatrix.sync.aligned.m8n8.x4.shared.b16 {%0,%1,%2,%3}, [%4];"
                 : "=r"(r[0]), "=r"(r[1]), "=r"(r[2]), "=r"(r[3]) : "r"(addr));
}

// ---------------------------------------------------------------------------
// fp32 -> fp16 conversion (grid-stride over float4s)
// ---------------------------------------------------------------------------
__global__ __launch_bounds__(256)
void f2h_kernel(const float* __restrict__ src, __half* __restrict__ dst, int n4)
{
    for (int i = blockIdx.x * blockDim.x + threadIdx.x; i < n4;
         i += gridDim.x * blockDim.x) {
        float4 v = reinterpret_cast<const float4*>(src)[i];
        uint2 u = make_uint2(pk(v.x, v.y), pk(v.z, v.w));
        reinterpret_cast<uint2*>(dst)[i] = u;
    }
}

// ---------------------------------------------------------------------------
// FP16 tensor GEMM (NT): C[M,N] = A[M,K] * B[N,K]^T, A/B fp16, C fp32.
// 128x128 tile, BK=32, 2-stage cp.async, ldmatrix.x4 fragments, 256 threads
// (8 warps 2m x 4n), warp tile 64x32, mma m16n8k16, fp32 accum.
// ---------------------------------------------------------------------------
template <bool FIRST>
__global__ __launch_bounds__(256)
void hgemm_tc(float* __restrict__ Carg, int K, int ldc)
{
    const __half* A = FIRST ? g_xh   : g_yh;
    const __half* Bw = FIRST ? g_ipwh : g_opwh;
    float*        C = FIRST ? g_xw  : Carg;

    __shared__ __half As[2][128 * SHH];
    __shared__ __half Bs[2][128 * SHH];

    const int tid  = threadIdx.x;
    const int lane = tid & 31;
    const int warp = tid >> 5;
    const int wm   = warp & 1;        // m offset wm*64
    const int wn   = warp >> 1;       // n offset wn*32
    const int grp  = lane >> 2;
    const int tig  = lane & 3;

    const int m0 = blockIdx.y * 128;
    const int n0 = blockIdx.x * 128;

    // cp.async staging: thread -> (row, 2 contiguous 16B chunks)
    const int lrow = tid >> 1;          // 0..127
    const int lc0  = (tid & 1) * 2;     // chunk 0 or 2 (8 halves each)

    const __half* gA = A  + (size_t)(m0 + lrow) * K + lc0 * 8;
    const __half* gB = Bw + (size_t)(n0 + lrow) * K + lc0 * 8;

    const uint32_t sA = (uint32_t)__cvta_generic_to_shared(As);
    const uint32_t sB = (uint32_t)__cvta_generic_to_shared(Bs);
    const uint32_t dA = sA + (lrow * SHH + lc0 * 8) * 2;
    const uint32_t dB = sB + (lrow * SHH + lc0 * 8) * 2;

    // ldmatrix lane offsets (bytes)
    //   A x4 tile (16 rows x 16 k): row = lane&15, kchunk = lane>>4
    const uint32_t laneA = ((lane & 15) * SHH + (lane >> 4) * 8) * 2;
    //   B x4 tile (16 n-rows x 16 k): row = (lane&7)+((lane>>4)<<3),
    //   kchunk = (lane>>3)&1
    const uint32_t laneB = (((lane & 7) + ((lane >> 4) << 3)) * SHH +
                            ((lane >> 3) & 1) * 8) * 2;

    float acc[4][4][4];
#pragma unroll
    for (int i = 0; i < 4; i++)
#pragma unroll
        for (int j = 0; j < 4; j++)
#pragma unroll
            for (int r = 0; r < 4; r++) acc[i][j][r] = 0.f;

    auto load_stage = [&](int st, int k0) {
        cp16(dA + st * STAGE_B, gA + k0);
        cp16(dA + st * STAGE_B + 16, gA + k0 + 8);
        cp16(dB + st * STAGE_B, gB + k0);
        cp16(dB + st * STAGE_B + 16, gB + k0 + 8);
    };

    load_stage(0, 0);
    asm volatile("cp.async.commit_group;\n" ::: "memory");

    const int NIT = K >> 5;
    for (int it = 0; it < NIT; ++it) {
        const int cur = it & 1;
        if (it + 1 < NIT) {
            load_stage(cur ^ 1, (it + 1) << 5);
            asm volatile("cp.async.commit_group;\n" ::: "memory");
            asm volatile("cp.async.wait_group 1;\n" ::: "memory");
        } else {
            asm volatile("cp.async.wait_group 0;\n" ::: "memory");
        }
        __syncthreads();

        const uint32_t aSt = sA + cur * STAGE_B;
        const uint32_t bSt = sB + cur * STAGE_B;
#pragma unroll
        for (int ks = 0; ks < 2; ks++) {
            uint32_t afr[4][4];
#pragma unroll
            for (int mt = 0; mt < 4; mt++)
                ldsm4(afr[mt], aSt + (wm * 64 + mt * 16) * (SHH * 2) + ks * 32 + laneA);
            uint32_t bfr[2][4];
#pragma unroll
            for (int np = 0; np < 2; np++)
                ldsm4(bfr[np], bSt + (wn * 32 + np * 16) * (SHH * 2) + ks * 32 + laneB);
#pragma unroll
            for (int mt = 0; mt < 4; mt++)
#pragma unroll
                for (int nt = 0; nt < 4; nt++)
                    mma_f16(acc[mt][nt], afr[mt], &bfr[nt >> 1][(nt & 1) * 2]);
        }
        __syncthreads();
    }

#pragma unroll
    for (int mt = 0; mt < 4; mt++) {
        const int row = m0 + wm * 64 + mt * 16 + grp;
#pragma unroll
        for (int nt = 0; nt < 4; nt++) {
            const int col = n0 + wn * 32 + nt * 8 + tig * 2;
            *reinterpret_cast<float2*>(&C[(size_t)row * ldc + col]) =
                make_float2(acc[mt][nt][0], acc[mt][nt][1]);
            *reinterpret_cast<float2*>(&C[(size_t)(row + 8) * ldc + col]) =
                make_float2(acc[mt][nt][2], acc[mt][nt][3]);
        }
    }
}

// ---------------------------------------------------------------------------
// K1b: skinny fp32 GEMM for the 16 "w" columns (exact fp32).
// ---------------------------------------------------------------------------
__global__ __launch_bounds__(256)
void wgemm_kernel(const float* __restrict__ x, const float* __restrict__ ipw)
{
    __shared__ float Xs[128][65];
    __shared__ float Ws[16][64];

    const int tid = threadIdx.x;
    const int col = tid & 15;
    const int rg  = tid >> 4;
    const int m0  = blockIdx.x * 128;

    float acc[8];
#pragma unroll
    for (int r = 0; r < 8; r++) acc[r] = 0.f;

    for (int k0 = 0; k0 < DM_; k0 += 64) {
        {
            const int row = tid >> 1;
            const int kk0 = (tid & 1) * 32;
#pragma unroll
            for (int q = 0; q < 8; q++) {
                float4 v = *reinterpret_cast<const float4*>(
                    &x[(size_t)(m0 + row) * DM_ + k0 + kk0 + q * 4]);
                Xs[row][kk0 + q * 4 + 0] = v.x;
                Xs[row][kk0 + q * 4 + 1] = v.y;
                Xs[row][kk0 + q * 4 + 2] = v.z;
                Xs[row][kk0 + q * 4 + 3] = v.w;
            }
        }
        {
            const int wr = tid >> 4;
            const int wk = (tid & 15) * 4;
            if (wr < 16) {
                float4 v = *reinterpret_cast<const float4*>(
                    &ipw[(size_t)(1024 + wr) * DM_ + k0 + wk]);
                Ws[wr][wk + 0] = v.x;
                Ws[wr][wk + 1] = v.y;
                Ws[wr][wk + 2] = v.z;
                Ws[wr][wk + 3] = v.w;
            }
        }
        __syncthreads();

#pragma unroll 8
        for (int k = 0; k < 64; k++) {
            const float wv = Ws[col][k];
#pragma unroll
            for (int r = 0; r < 8; r++)
                acc[r] = fmaf(Xs[rg + r * 16][k], wv, acc[r]);
        }
        __syncthreads();
    }

#pragma unroll
    for (int r = 0; r < 8; r++)
        g_xw[(size_t)(m0 + rg + r * 16) * E_ + 1024 + col] = acc[r];
}

// ---------------------------------------------------------------------------
// K2: per-(b,h,c) chunk stats — rolling conv window.
// ---------------------------------------------------------------------------
__global__ __launch_bounds__(64)
void chunk_stats_kernel(const float* __restrict__ conv_w,
                        const float* __restrict__ conv_b,
                        const float* __restrict__ w_base)
{
    const int c = blockIdx.x, h = blockIdx.y, b = blockIdx.z;
    const int n = threadIdx.x;

    __shared__ float sS[64];
    __shared__ float sE[64];
    __shared__ float sMin;

    const int ch = h * 64 + n;
    const float cw0 = conv_w[ch * 4 + 0];
    const float cw1 = conv_w[ch * 4 + 1];
    const float cw2 = conv_w[ch * 4 + 2];
    const float cw3 = conv_w[ch * 4 + 3];
    const float cb  = conv_b[ch];

    const int s0 = c * 64;
    const float* xwb = g_xw + (size_t)b * S_ * E_;
    const float* xp  = xwb + (size_t)s0 * E_ + h * 64 + n;

    float xm3 = 0.f, xm2 = 0.f, xm1 = 0.f;
    if (c > 0) {
        xm3 = xp[-(ptrdiff_t)(3 * E_)];
        xm2 = xp[-(ptrdiff_t)(2 * E_)];
        xm1 = xp[-(ptrdiff_t)(1 * E_)];
    }

    sS[n] = xwb[(size_t)(s0 + n) * E_ + 1024 + h] * w_base[h];
    __syncthreads();

    if (n == 0) {
        float run = 0.f, mn = 3.4e38f;
        for (int i = 0; i < 64; i++) {
            run += sS[i];
            sS[i] = run;
            mn = fminf(mn, run);
        }
        sMin = mn;
    }
    __syncthreads();
    sE[n] = __expf(-sS[n]);
    __syncthreads();

    float r = 0.f, rn = 0.f;
#pragma unroll 4
    for (int i = 0; i < 64; i++) {
        const float x0 = xp[(size_t)i * E_];
        const float xv = cb + cw0 * xm3 + cw1 * xm2 + cw2 * xm1 + cw3 * x0;
        xm3 = xm2; xm2 = xm1; xm1 = x0;
        const float e = sE[i];
        r  = fmaf(e, xv, r);
        rn += e;
    }

    const float sc  = __expf(sMin);
    const int   idx = (b * H_ + h) * C_ + c;
    g_states[idx * N_ + n] = sc * r;
    if (n == 0) {
        g_cnorm[idx] = sc * rn;
        g_T[idx]     = sS[63];
    }
}

// ---------------------------------------------------------------------------
// K3: per-(b,h) cross-chunk scan — 256 threads.
// ---------------------------------------------------------------------------
__global__ __launch_bounds__(256)
void chunk_scan_kernel()
{
    const int h = blockIdx.x, b = blockIdx.y;
    const int tid = threadIdx.x;
    const int n  = tid & 63;
    const int zq = tid >> 6;

    __shared__ float G[65];
    __shared__ float MP[64];
    __shared__ float W[64][64];
    __shared__ float st[64][64];
    __shared__ float cn[64];

    const int base = (b * H_ + h) * C_;

    for (int idx = tid; idx < 4096; idx += 256)
        st[idx >> 6][idx & 63] = g_states[(size_t)base * N_ + idx];
    if (tid < 64) cn[tid] = g_cnorm[base + tid];
    __syncthreads();

    if (tid == 0) {
        float run = 0.f;
        G[0] = 0.f;
        for (int c = 0; c < 64; c++) { run += g_T[base + c]; G[c + 1] = run; }
        float mn = 3.4e38f;
        for (int z = 0; z < 64; z++) { mn = fminf(mn, G[z]); MP[z] = mn; }
    }
    __syncthreads();

    for (int idx = tid; idx < 4096; idx += 256) {
        const int z = idx >> 6, cp = idx & 63;
        W[z][cp] = (cp < z) ? __expf(MP[z] - G[cp + 1]) : 0.f;
    }
    __syncthreads();

    for (int z = zq; z < 64; z += 4) {
        float accv = 0.f;
        for (int cp = 0; cp < z; cp++) accv = fmaf(W[z][cp], st[cp][n], accv);
        g_nstates[(base + z) * N_ + n] = accv;
    }
    if (tid < 64) {
        float accn = 0.f;
        for (int cp = 0; cp < tid; cp++) accn = fmaf(W[tid][cp], cn[cp], accn);
        g_nnorm[base + tid] = accn;
    }
}

// ---------------------------------------------------------------------------
// K4: per-(b,h,c) combine -> y (written as fp16 for GEMM2).
// ---------------------------------------------------------------------------
__global__ __launch_bounds__(64)
void combine_kernel(const float* __restrict__ conv_w,
                    const float* __restrict__ conv_b,
                    const float* __restrict__ w_base)
{
    const int c = blockIdx.x, h = blockIdx.y, b = blockIdx.z;
    const int n = threadIdx.x;

    __shared__ float sS[64];
    __shared__ float sE[64], sEMP[64], sSDO[64];
    __shared__ float sMP[64];
    __shared__ float sMax;

    const int ch = h * 64 + n;
    const float cw0 = conv_w[ch * 4 + 0];
    const float cw1 = conv_w[ch * 4 + 1];
    const float cw2 = conv_w[ch * 4 + 2];
    const float cw3 = conv_w[ch * 4 + 3];
    const float cb  = conv_b[ch];

    const int s0 = c * 64;
    const float* xwb = g_xw + (size_t)b * S_ * E_;
    const float* xp  = xwb + (size_t)s0 * E_ + h * 64 + n;

    float xm3 = 0.f, xm2 = 0.f, xm1 = 0.f;
    if (c > 0) {
        xm3 = xp[-(ptrdiff_t)(3 * E_)];
        xm2 = xp[-(ptrdiff_t)(2 * E_)];
        xm1 = xp[-(ptrdiff_t)(1 * E_)];
    }

    sS[n] = xwb[(size_t)(s0 + n) * E_ + 1024 + h] * w_base[h];
    __syncthreads();

    if (n == 0) {
        float run = 0.f, mn = 3.4e38f, mx = -3.4e38f;
        for (int i = 0; i < 64; i++) {
            run += sS[i];
            sS[i] = run;
            mn = fminf(mn, run);
            sMP[i] = mn;
            mx = fmaxf(mx, run);
        }
        sMax = mx;
    }
    __syncthreads();
    sE[n]   = __expf(-sS[n]);
    sEMP[n] = __expf(sMP[n]);
    sSDO[n] = __expf(sS[n] - sMax);
    __syncthreads();

    const int idx = (b * H_ + h) * C_ + c;
    const float ns = g_nstates[idx * N_ + n];
    const float nn = g_nnorm[idx];

    float r = 0.f, rn = 0.f;
    __half* yout = g_yh + (size_t)(b * S_ + s0) * DM_ + h * 64 + n;

#pragma unroll 4
    for (int i = 0; i < 64; i++) {
        const float x0 = xp[(size_t)i * E_];
        const float xv = cb + cw0 * xm3 + cw1 * xm2 + cw2 * xm1 + cw3 * x0;
        xm3 = xm2; xm2 = xm1; xm1 = x0;
        const float e = sE[i];
        r  = fmaf(e, xv, r);
        rn += e;
        const float emp = sEMP[i];
        const float sdo = sSDO[i];
        const float num = fmaf(sdo, ns, emp * r);
        const float den = fmaf(sdo, nn, emp * rn);
        yout[(size_t)i * DM_] = __float2half_rn(num / den);
    }
}

// ---------------------------------------------------------------------------
// Launch
// ---------------------------------------------------------------------------
extern "C" void kernel_launch(void* const* d_in, const int* in_sizes, int n_in,
                              void* d_out, int out_size)
{
    const float *x = nullptr, *ipw = nullptr, *cw = nullptr,
                *cb = nullptr, *wb = nullptr, *opw = nullptr;
    for (int i = 0; i < n_in; i++) {
        switch (in_sizes[i]) {
            case M_ * DM_:  x   = (const float*)d_in[i]; break;
            case E_ * DM_:  ipw = (const float*)d_in[i]; break;
            case DM_ * 4:   cw  = (const float*)d_in[i]; break;
            case DM_:       cb  = (const float*)d_in[i]; break;
            case H_:        wb  = (const float*)d_in[i]; break;
            case DM_ * DM_: opw = (const float*)d_in[i]; break;
        }
    }

    __half *xh, *ipwh, *opwh;
    cudaGetSymbolAddress((void**)&xh,   g_xh);
    cudaGetSymbolAddress((void**)&ipwh, g_ipwh);
    cudaGetSymbolAddress((void**)&opwh, g_opwh);

    // C0: fp32 -> fp16 operand conversion
    f2h_kernel<<<4096, 256>>>(x, xh, M_ * DM_ / 4);
    f2h_kernel<<<512, 256>>>(ipw, ipwh, DM_ * DM_ / 4);   // first 1024 rows only
    f2h_kernel<<<512, 256>>>(opw, opwh, DM_ * DM_ / 4);

    // K1a: xi = x @ in_proj_w[:1024]^T (fp16 TC, cp.async + ldmatrix)
    hgemm_tc<true><<<dim3(DM_ / 128, M_ / 128), 256>>>(nullptr, DM_, E_);

    // K1b: w = x @ in_proj_w[1024:]^T (fp32 exact)
    wgemm_kernel<<<M_ / 128, 256>>>(x, ipw);

    // K2: per-chunk stats
    chunk_stats_kernel<<<dim3(C_, H_, B_), 64>>>(cw, cb, wb);

    // K3: cross-chunk scan
    chunk_scan_kernel<<<dim3(H_, B_), 256>>>();

    // K4: combine -> y (fp16)
    combine_kernel<<<dim3(C_, H_, B_), 64>>>(cw, cb, wb);

    // K5: out = y @ out_proj_w^T (fp16 TC)
    hgemm_tc<false><<<dim3(DM_ / 128, M_ / 128), 256>>>(
        (float*)d_out, DM_, DM_);
}

// round 7
// speedup vs baseline: 1.5513x; 1.0125x over previous
#include <cuda_runtime.h>
#include <cuda_fp16.h>
#include <cstdint>
#include <cstddef>

// ---------------------------------------------------------------------------
// DecayBlock (Mamba-2 SSD block) — round 7: raise FLOP per smem byte.
//   R6 showed tensor(41%) ~= L1(44%): GEMM co-limited by smem bandwidth.
//   Fix: warp tile 64x32 -> 64x64 (block 128x256), 3-stage cp.async ring.
//   Per-k16: 8 ldsm4 feed 32 MMAs -> ~24 FLOP/smem-byte (was ~16).
// ---------------------------------------------------------------------------

namespace {
constexpr int B_  = 8;
constexpr int S_  = 4096;
constexpr int DM_ = 1024;
constexpr int H_  = 16;
constexpr int N_  = 64;
constexpr int C_  = 64;
constexpr int E_  = 1040;
constexpr int M_  = B_ * S_;
constexpr int SHH = 40;                    // smem row stride (32 halves + 8 pad)
constexpr int A_STAGE = 128 * SHH * 2;     // 10240 B
constexpr int B_STAGE = 256 * SHH * 2;     // 20480 B
constexpr int NSTAGE  = 3;
constexpr int GEMM_SMEM = NSTAGE * (A_STAGE + B_STAGE);   // 92160 B
}

// Scratch (allocation-free: __device__ globals)
__device__ __align__(16) float  g_xw[(size_t)M_ * E_];
__device__ __align__(16) __half g_xh[(size_t)M_ * DM_];
__device__ __align__(16) __half g_yh[(size_t)M_ * DM_];
__device__ __align__(16) __half g_ipwh[(size_t)DM_ * DM_];
__device__ __align__(16) __half g_opwh[(size_t)DM_ * DM_];
__device__ __align__(16) float g_states[B_ * H_ * C_ * N_];
__device__ float g_cnorm[B_ * H_ * C_];
__device__ float g_T[B_ * H_ * C_];
__device__ __align__(16) float g_nstates[B_ * H_ * C_ * N_];
__device__ float g_nnorm[B_ * H_ * C_];

__device__ __forceinline__ uint32_t pk(float lo, float hi) {
    __half2 h = __floats2half2_rn(lo, hi);
    return *reinterpret_cast<uint32_t*>(&h);
}

__device__ __forceinline__ void mma_f16(float* c, const uint32_t* a, const uint32_t* b) {
    asm volatile(
        "mma.sync.aligned.m16n8k16.row.col.f32.f16.f16.f32 "
        "{%0,%1,%2,%3}, {%4,%5,%6,%7}, {%8,%9}, {%0,%1,%2,%3};\n"
        : "+f"(c[0]), "+f"(c[1]), "+f"(c[2]), "+f"(c[3])
        : "r"(a[0]), "r"(a[1]), "r"(a[2]), "r"(a[3]), "r"(b[0]), "r"(b[1]));
}

__device__ __forceinline__ void cp16(uint32_t smem, const void* gmem) {
    asm volatile("cp.async.cg.shared.global [%0], [%1], 16;\n" :: "r"(smem), "l"(gmem));
}

__device__ __forceinline__ void ldsm4(uint32_t* r, uint32_t addr) {
    asm volatile("ldmatrix.sync.aligned.m8n8.x4.shared.b16 {%0,%1,%2,%3}, [%4];"
                 : "=r"(r[0]), "=r"(r[1]), "=r"(r[2]), "=r"(r[3]) : "r"(addr));
}

// ---------------------------------------------------------------------------
// fp32 -> fp16 conversion (grid-stride over float4s)
// ---------------------------------------------------------------------------
__global__ __launch_bounds__(256)
void f2h_kernel(const float* __restrict__ src, __half* __restrict__ dst, int n4)
{
    for (int i = blockIdx.x * blockDim.x + threadIdx.x; i < n4;
         i += gridDim.x * blockDim.x) {
        float4 v = reinterpret_cast<const float4*>(src)[i];
        uint2 u = make_uint2(pk(v.x, v.y), pk(v.z, v.w));
        reinterpret_cast<uint2*>(dst)[i] = u;
    }
}

// ---------------------------------------------------------------------------
// FP16 tensor GEMM (NT): C[M,N] = A[M,K] * B[N,K]^T, A/B fp16, C fp32.
// Block tile 128x256, warp tile 64x64 (8 warps, 2m x 4n), BK=32,
// 3-stage cp.async ring, ldmatrix.x4 fragments, mma m16n8k16, fp32 accum.
// ---------------------------------------------------------------------------
template <bool FIRST>
__global__ __launch_bounds__(256)
void hgemm_tc(float* __restrict__ Carg, int K, int ldc)
{
    const __half* A  = FIRST ? g_xh   : g_yh;
    const __half* Bw = FIRST ? g_ipwh : g_opwh;
    float*        C  = FIRST ? g_xw   : Carg;

    extern __shared__ __align__(16) char smem[];
    const uint32_t sbase = (uint32_t)__cvta_generic_to_shared(smem);

    const int tid  = threadIdx.x;
    const int lane = tid & 31;
    const int warp = tid >> 5;
    const int wm   = warp & 1;        // m offset wm*64
    const int wn   = warp >> 1;       // n offset wn*64
    const int grp  = lane >> 2;
    const int tig  = lane & 3;

    const int m0 = blockIdx.y * 128;
    const int n0 = blockIdx.x * 256;

    // cp.async staging: A 128 rows (1 row/2 threads, 2x16B each),
    //                   B 256 rows (2 rows/2 threads, 2x16B each)
    const int lrow = tid >> 1;            // 0..127
    const int lc0  = (tid & 1) * 16;      // half offset 0 or 16

    const __half* gA  = A  + (size_t)(m0 + lrow) * K + lc0;
    const __half* gB0 = Bw + (size_t)(n0 + lrow) * K + lc0;
    const __half* gB1 = Bw + (size_t)(n0 + lrow + 128) * K + lc0;

    const uint32_t dAoff = (uint32_t)(lrow * SHH + lc0) * 2;
    const uint32_t dB0off = dAoff;                      // same row pattern
    const uint32_t dB1off = (uint32_t)((lrow + 128) * SHH + lc0) * 2;

    // ldmatrix lane offsets (bytes)
    const uint32_t laneA = ((lane & 15) * SHH + (lane >> 4) * 8) * 2;
    const uint32_t laneB = (((lane & 7) + ((lane >> 4) << 3)) * SHH +
                            ((lane >> 3) & 1) * 8) * 2;

    float acc[4][8][4];
#pragma unroll
    for (int i = 0; i < 4; i++)
#pragma unroll
        for (int j = 0; j < 8; j++)
#pragma unroll
            for (int r = 0; r < 4; r++) acc[i][j][r] = 0.f;

    auto aBase = [&](int st) { return sbase + st * A_STAGE; };
    auto bBase = [&](int st) { return sbase + NSTAGE * A_STAGE + st * B_STAGE; };

    auto load_stage = [&](int st, int k0) {
        cp16(aBase(st) + dAoff,       gA + k0);
        cp16(aBase(st) + dAoff + 16,  gA + k0 + 8);
        cp16(bBase(st) + dB0off,      gB0 + k0);
        cp16(bBase(st) + dB0off + 16, gB0 + k0 + 8);
        cp16(bBase(st) + dB1off,      gB1 + k0);
        cp16(bBase(st) + dB1off + 16, gB1 + k0 + 8);
    };

    const int NIT = K >> 5;
    load_stage(0, 0);
    asm volatile("cp.async.commit_group;\n" ::: "memory");
    load_stage(1, 32);
    asm volatile("cp.async.commit_group;\n" ::: "memory");

    for (int it = 0; it < NIT; ++it) {
        const int cur = it % NSTAGE;
        if (it < NIT - 1) {
            asm volatile("cp.async.wait_group 1;\n" ::: "memory");
        } else {
            asm volatile("cp.async.wait_group 0;\n" ::: "memory");
        }
        __syncthreads();

        if (it + 2 < NIT) {
            load_stage((it + 2) % NSTAGE, (it + 2) << 5);
            asm volatile("cp.async.commit_group;\n" ::: "memory");
        }

        const uint32_t aSt = aBase(cur);
        const uint32_t bSt = bBase(cur);
#pragma unroll
        for (int ks = 0; ks < 2; ks++) {
            uint32_t afr[4][4];
#pragma unroll
            for (int mt = 0; mt < 4; mt++)
                ldsm4(afr[mt], aSt + (wm * 64 + mt * 16) * (SHH * 2) + ks * 32 + laneA);
            uint32_t bfr[4][4];
#pragma unroll
            for (int np = 0; np < 4; np++)
                ldsm4(bfr[np], bSt + (wn * 64 + np * 16) * (SHH * 2) + ks * 32 + laneB);
#pragma unroll
            for (int mt = 0; mt < 4; mt++)
#pragma unroll
                for (int nt = 0; nt < 8; nt++)
                    mma_f16(acc[mt][nt], afr[mt], &bfr[nt >> 1][(nt & 1) * 2]);
        }
    }
    __syncthreads();

#pragma unroll
    for (int mt = 0; mt < 4; mt++) {
        const int row = m0 + wm * 64 + mt * 16 + grp;
#pragma unroll
        for (int nt = 0; nt < 8; nt++) {
            const int col = n0 + wn * 64 + nt * 8 + tig * 2;
            *reinterpret_cast<float2*>(&C[(size_t)row * ldc + col]) =
                make_float2(acc[mt][nt][0], acc[mt][nt][1]);
            *reinterpret_cast<float2*>(&C[(size_t)(row + 8) * ldc + col]) =
                make_float2(acc[mt][nt][2], acc[mt][nt][3]);
        }
    }
}

// ---------------------------------------------------------------------------
// K1b: skinny fp32 GEMM for the 16 "w" columns (exact fp32).
// ---------------------------------------------------------------------------
__global__ __launch_bounds__(256)
void wgemm_kernel(const float* __restrict__ x, const float* __restrict__ ipw)
{
    __shared__ float Xs[128][65];
    __shared__ float Ws[16][64];

    const int tid = threadIdx.x;
    const int col = tid & 15;
    const int rg  = tid >> 4;
    const int m0  = blockIdx.x * 128;

    float acc[8];
#pragma unroll
    for (int r = 0; r < 8; r++) acc[r] = 0.f;

    for (int k0 = 0; k0 < DM_; k0 += 64) {
        {
            const int row = tid >> 1;
            const int kk0 = (tid & 1) * 32;
#pragma unroll
            for (int q = 0; q < 8; q++) {
                float4 v = *reinterpret_cast<const float4*>(
                    &x[(size_t)(m0 + row) * DM_ + k0 + kk0 + q * 4]);
                Xs[row][kk0 + q * 4 + 0] = v.x;
                Xs[row][kk0 + q * 4 + 1] = v.y;
                Xs[row][kk0 + q * 4 + 2] = v.z;
                Xs[row][kk0 + q * 4 + 3] = v.w;
            }
        }
        {
            const int wr = tid >> 4;
            const int wk = (tid & 15) * 4;
            if (wr < 16) {
                float4 v = *reinterpret_cast<const float4*>(
                    &ipw[(size_t)(1024 + wr) * DM_ + k0 + wk]);
                Ws[wr][wk + 0] = v.x;
                Ws[wr][wk + 1] = v.y;
                Ws[wr][wk + 2] = v.z;
                Ws[wr][wk + 3] = v.w;
            }
        }
        __syncthreads();

#pragma unroll 8
        for (int k = 0; k < 64; k++) {
            const float wv = Ws[col][k];
#pragma unroll
            for (int r = 0; r < 8; r++)
                acc[r] = fmaf(Xs[rg + r * 16][k], wv, acc[r]);
        }
        __syncthreads();
    }

#pragma unroll
    for (int r = 0; r < 8; r++)
        g_xw[(size_t)(m0 + rg + r * 16) * E_ + 1024 + col] = acc[r];
}

// ---------------------------------------------------------------------------
// K2: per-(b,h,c) chunk stats — rolling conv window.
// ---------------------------------------------------------------------------
__global__ __launch_bounds__(64)
void chunk_stats_kernel(const float* __restrict__ conv_w,
                        const float* __restrict__ conv_b,
                        const float* __restrict__ w_base)
{
    const int c = blockIdx.x, h = blockIdx.y, b = blockIdx.z;
    const int n = threadIdx.x;

    __shared__ float sS[64];
    __shared__ float sE[64];
    __shared__ float sMin;

    const int ch = h * 64 + n;
    const float cw0 = conv_w[ch * 4 + 0];
    const float cw1 = conv_w[ch * 4 + 1];
    const float cw2 = conv_w[ch * 4 + 2];
    const float cw3 = conv_w[ch * 4 + 3];
    const float cb  = conv_b[ch];

    const int s0 = c * 64;
    const float* xwb = g_xw + (size_t)b * S_ * E_;
    const float* xp  = xwb + (size_t)s0 * E_ + h * 64 + n;

    float xm3 = 0.f, xm2 = 0.f, xm1 = 0.f;
    if (c > 0) {
        xm3 = xp[-(ptrdiff_t)(3 * E_)];
        xm2 = xp[-(ptrdiff_t)(2 * E_)];
        xm1 = xp[-(ptrdiff_t)(1 * E_)];
    }

    sS[n] = xwb[(size_t)(s0 + n) * E_ + 1024 + h] * w_base[h];
    __syncthreads();

    if (n == 0) {
        float run = 0.f, mn = 3.4e38f;
        for (int i = 0; i < 64; i++) {
            run += sS[i];
            sS[i] = run;
            mn = fminf(mn, run);
        }
        sMin = mn;
    }
    __syncthreads();
    sE[n] = __expf(-sS[n]);
    __syncthreads();

    float r = 0.f, rn = 0.f;
#pragma unroll 4
    for (int i = 0; i < 64; i++) {
        const float x0 = xp[(size_t)i * E_];
        const float xv = cb + cw0 * xm3 + cw1 * xm2 + cw2 * xm1 + cw3 * x0;
        xm3 = xm2; xm2 = xm1; xm1 = x0;
        const float e = sE[i];
        r  = fmaf(e, xv, r);
        rn += e;
    }

    const float sc  = __expf(sMin);
    const int   idx = (b * H_ + h) * C_ + c;
    g_states[idx * N_ + n] = sc * r;
    if (n == 0) {
        g_cnorm[idx] = sc * rn;
        g_T[idx]     = sS[63];
    }
}

// ---------------------------------------------------------------------------
// K3: per-(b,h) cross-chunk scan — 256 threads.
// ---------------------------------------------------------------------------
__global__ __launch_bounds__(256)
void chunk_scan_kernel()
{
    const int h = blockIdx.x, b = blockIdx.y;
    const int tid = threadIdx.x;
    const int n  = tid & 63;
    const int zq = tid >> 6;

    __shared__ float G[65];
    __shared__ float MP[64];
    __shared__ float W[64][64];
    __shared__ float st[64][64];
    __shared__ float cn[64];

    const int base = (b * H_ + h) * C_;

    for (int idx = tid; idx < 4096; idx += 256)
        st[idx >> 6][idx & 63] = g_states[(size_t)base * N_ + idx];
    if (tid < 64) cn[tid] = g_cnorm[base + tid];
    __syncthreads();

    if (tid == 0) {
        float run = 0.f;
        G[0] = 0.f;
        for (int c = 0; c < 64; c++) { run += g_T[base + c]; G[c + 1] = run; }
        float mn = 3.4e38f;
        for (int z = 0; z < 64; z++) { mn = fminf(mn, G[z]); MP[z] = mn; }
    }
    __syncthreads();

    for (int idx = tid; idx < 4096; idx += 256) {
        const int z = idx >> 6, cp = idx & 63;
        W[z][cp] = (cp < z) ? __expf(MP[z] - G[cp + 1]) : 0.f;
    }
    __syncthreads();

    for (int z = zq; z < 64; z += 4) {
        float accv = 0.f;
        for (int cp = 0; cp < z; cp++) accv = fmaf(W[z][cp], st[cp][n], accv);
        g_nstates[(base + z) * N_ + n] = accv;
    }
    if (tid < 64) {
        float accn = 0.f;
        for (int cp = 0; cp < tid; cp++) accn = fmaf(W[tid][cp], cn[cp], accn);
        g_nnorm[base + tid] = accn;
    }
}

// ---------------------------------------------------------------------------
// K4: per-(b,h,c) combine -> y (written as fp16 for GEMM2).
// ---------------------------------------------------------------------------
__global__ __launch_bounds__(64)
void combine_kernel(const float* __restrict__ conv_w,
                    const float* __restrict__ conv_b,
                    const float* __restrict__ w_base)
{
    const int c = blockIdx.x, h = blockIdx.y, b = blockIdx.z;
    const int n = threadIdx.x;

    __shared__ float sS[64];
    __shared__ float sE[64], sEMP[64], sSDO[64];
    __shared__ float sMP[64];
    __shared__ float sMax;

    const int ch = h * 64 + n;
    const float cw0 = conv_w[ch * 4 + 0];
    const float cw1 = conv_w[ch * 4 + 1];
    const float cw2 = conv_w[ch * 4 + 2];
    const float cw3 = conv_w[ch * 4 + 3];
    const float cb  = conv_b[ch];

    const int s0 = c * 64;
    const float* xwb = g_xw + (size_t)b * S_ * E_;
    const float* xp  = xwb + (size_t)s0 * E_ + h * 64 + n;

    float xm3 = 0.f, xm2 = 0.f, xm1 = 0.f;
    if (c > 0) {
        xm3 = xp[-(ptrdiff_t)(3 * E_)];
        xm2 = xp[-(ptrdiff_t)(2 * E_)];
        xm1 = xp[-(ptrdiff_t)(1 * E_)];
    }

    sS[n] = xwb[(size_t)(s0 + n) * E_ + 1024 + h] * w_base[h];
    __syncthreads();

    if (n == 0) {
        float run = 0.f, mn = 3.4e38f, mx = -3.4e38f;
        for (int i = 0; i < 64; i++) {
            run += sS[i];
            sS[i] = run;
            mn = fminf(mn, run);
            sMP[i] = mn;
            mx = fmaxf(mx, run);
        }
        sMax = mx;
    }
    __syncthreads();
    sE[n]   = __expf(-sS[n]);
    sEMP[n] = __expf(sMP[n]);
    sSDO[n] = __expf(sS[n] - sMax);
    __syncthreads();

    const int idx = (b * H_ + h) * C_ + c;
    const float ns = g_nstates[idx * N_ + n];
    const float nn = g_nnorm[idx];

    float r = 0.f, rn = 0.f;
    __half* yout = g_yh + (size_t)(b * S_ + s0) * DM_ + h * 64 + n;

#pragma unroll 4
    for (int i = 0; i < 64; i++) {
        const float x0 = xp[(size_t)i * E_];
        const float xv = cb + cw0 * xm3 + cw1 * xm2 + cw2 * xm1 + cw3 * x0;
        xm3 = xm2; xm2 = xm1; xm1 = x0;
        const float e = sE[i];
        r  = fmaf(e, xv, r);
        rn += e;
        const float emp = sEMP[i];
        const float sdo = sSDO[i];
        const float num = fmaf(sdo, ns, emp * r);
        const float den = fmaf(sdo, nn, emp * rn);
        yout[(size_t)i * DM_] = __float2half_rn(num / den);
    }
}

// ---------------------------------------------------------------------------
// Launch
// ---------------------------------------------------------------------------
extern "C" void kernel_launch(void* const* d_in, const int* in_sizes, int n_in,
                              void* d_out, int out_size)
{
    const float *x = nullptr, *ipw = nullptr, *cw = nullptr,
                *cb = nullptr, *wb = nullptr, *opw = nullptr;
    for (int i = 0; i < n_in; i++) {
        switch (in_sizes[i]) {
            case M_ * DM_:  x   = (const float*)d_in[i]; break;
            case E_ * DM_:  ipw = (const float*)d_in[i]; break;
            case DM_ * 4:   cw  = (const float*)d_in[i]; break;
            case DM_:       cb  = (const float*)d_in[i]; break;
            case H_:        wb  = (const float*)d_in[i]; break;
            case DM_ * DM_: opw = (const float*)d_in[i]; break;
        }
    }

    __half *xh, *ipwh, *opwh;
    cudaGetSymbolAddress((void**)&xh,   g_xh);
    cudaGetSymbolAddress((void**)&ipwh, g_ipwh);
    cudaGetSymbolAddress((void**)&opwh, g_opwh);

    static bool attr_done = false;
    if (!attr_done) {
        cudaFuncSetAttribute(hgemm_tc<true>,
                             cudaFuncAttributeMaxDynamicSharedMemorySize, GEMM_SMEM);
        cudaFuncSetAttribute(hgemm_tc<false>,
                             cudaFuncAttributeMaxDynamicSharedMemorySize, GEMM_SMEM);
        attr_done = true;
    }

    // C0: fp32 -> fp16 operand conversion
    f2h_kernel<<<4096, 256>>>(x, xh, M_ * DM_ / 4);
    f2h_kernel<<<512, 256>>>(ipw, ipwh, DM_ * DM_ / 4);   // first 1024 rows only
    f2h_kernel<<<512, 256>>>(opw, opwh, DM_ * DM_ / 4);

    // K1a: xi = x @ in_proj_w[:1024]^T (fp16 TC, 128x256 tile)
    hgemm_tc<true><<<dim3(DM_ / 256, M_ / 128), 256, GEMM_SMEM>>>(nullptr, DM_, E_);

    // K1b: w = x @ in_proj_w[1024:]^T (fp32 exact)
    wgemm_kernel<<<M_ / 128, 256>>>(x, ipw);

    // K2: per-chunk stats
    chunk_stats_kernel<<<dim3(C_, H_, B_), 64>>>(cw, cb, wb);

    // K3: cross-chunk scan
    chunk_scan_kernel<<<dim3(H_, B_), 256>>>();

    // K4: combine -> y (fp16)
    combine_kernel<<<dim3(C_, H_, B_), 64>>>(cw, cb, wb);

    // K5: out = y @ out_proj_w^T (fp16 TC, 128x256 tile)
    hgemm_tc<false><<<dim3(DM_ / 256, M_ / 128), 256, GEMM_SMEM>>>(
        (float*)d_out, DM_, DM_);
}

// round 8
// speedup vs baseline: 1.6739x; 1.0790x over previous
#include <cuda_runtime.h>
#include <cuda_fp16.h>
#include <cstdint>
#include <cstddef>

// ---------------------------------------------------------------------------
// DecayBlock (Mamba-2 SSD block) — round 8: warps x intensity together.
//   R6: 16 warps/SM but smem-bw-bound (L1 44%). R7: intensity up (L1 35%)
//   but 8 warps can't hide LDSM/barrier latency (tensor stuck 42%).
//   R8: 128x256 block tile, 512 threads (16 warps, warp tile 32x64),
//   3-stage cp.async, 1 sync/iter. Latency hidden AND bandwidth ok.
// ---------------------------------------------------------------------------

namespace {
constexpr int B_  = 8;
constexpr int S_  = 4096;
constexpr int DM_ = 1024;
constexpr int H_  = 16;
constexpr int N_  = 64;
constexpr int C_  = 64;
constexpr int E_  = 1040;
constexpr int M_  = B_ * S_;
constexpr int SHH = 40;                    // smem row stride (32 halves + 8 pad)
constexpr int A_STAGE = 128 * SHH * 2;     // 10240 B
constexpr int B_STAGE = 256 * SHH * 2;     // 20480 B
constexpr int NSTAGE  = 3;
constexpr int GEMM_SMEM = NSTAGE * (A_STAGE + B_STAGE);   // 92160 B
}

// Scratch (allocation-free: __device__ globals)
__device__ __align__(16) float  g_xw[(size_t)M_ * E_];
__device__ __align__(16) __half g_xh[(size_t)M_ * DM_];
__device__ __align__(16) __half g_yh[(size_t)M_ * DM_];
__device__ __align__(16) __half g_ipwh[(size_t)DM_ * DM_];
__device__ __align__(16) __half g_opwh[(size_t)DM_ * DM_];
__device__ __align__(16) float g_states[B_ * H_ * C_ * N_];
__device__ float g_cnorm[B_ * H_ * C_];
__device__ float g_T[B_ * H_ * C_];
__device__ __align__(16) float g_nstates[B_ * H_ * C_ * N_];
__device__ float g_nnorm[B_ * H_ * C_];

__device__ __forceinline__ uint32_t pk(float lo, float hi) {
    __half2 h = __floats2half2_rn(lo, hi);
    return *reinterpret_cast<uint32_t*>(&h);
}

__device__ __forceinline__ void mma_f16(float* c, const uint32_t* a, const uint32_t* b) {
    asm volatile(
        "mma.sync.aligned.m16n8k16.row.col.f32.f16.f16.f32 "
        "{%0,%1,%2,%3}, {%4,%5,%6,%7}, {%8,%9}, {%0,%1,%2,%3};\n"
        : "+f"(c[0]), "+f"(c[1]), "+f"(c[2]), "+f"(c[3])
        : "r"(a[0]), "r"(a[1]), "r"(a[2]), "r"(a[3]), "r"(b[0]), "r"(b[1]));
}

__device__ __forceinline__ void cp16(uint32_t smem, const void* gmem) {
    asm volatile("cp.async.cg.shared.global [%0], [%1], 16;\n" :: "r"(smem), "l"(gmem));
}

__device__ __forceinline__ void ldsm4(uint32_t* r, uint32_t addr) {
    asm volatile("ldmatrix.sync.aligned.m8n8.x4.shared.b16 {%0,%1,%2,%3}, [%4];"
                 : "=r"(r[0]), "=r"(r[1]), "=r"(r[2]), "=r"(r[3]) : "r"(addr));
}

// ---------------------------------------------------------------------------
// fp32 -> fp16 conversion (grid-stride over float4s)
// ---------------------------------------------------------------------------
__global__ __launch_bounds__(256)
void f2h_kernel(const float* __restrict__ src, __half* __restrict__ dst, int n4)
{
    for (int i = blockIdx.x * blockDim.x + threadIdx.x; i < n4;
         i += gridDim.x * blockDim.x) {
        float4 v = reinterpret_cast<const float4*>(src)[i];
        uint2 u = make_uint2(pk(v.x, v.y), pk(v.z, v.w));
        reinterpret_cast<uint2*>(dst)[i] = u;
    }
}

// ---------------------------------------------------------------------------
// FP16 tensor GEMM (NT): C[M,N] = A[M,K] * B[N,K]^T, A/B fp16, C fp32.
// Block tile 128x256, 512 threads = 16 warps (4m x 4n), warp tile 32x64,
// BK=32, 3-stage cp.async ring, ldmatrix.x4, mma m16n8k16, fp32 accum.
// ---------------------------------------------------------------------------
template <bool FIRST>
__global__ __launch_bounds__(512)
void hgemm_tc(float* __restrict__ Carg, int K, int ldc)
{
    const __half* A  = FIRST ? g_xh   : g_yh;
    const __half* Bw = FIRST ? g_ipwh : g_opwh;
    float*        C  = FIRST ? g_xw   : Carg;

    extern __shared__ __align__(16) char smem[];
    const uint32_t sbase = (uint32_t)__cvta_generic_to_shared(smem);

    const int tid  = threadIdx.x;
    const int lane = tid & 31;
    const int warp = tid >> 5;
    const int wm   = warp & 3;        // m offset wm*32
    const int wn   = warp >> 2;       // n offset wn*64
    const int grp  = lane >> 2;
    const int tig  = lane & 3;

    const int m0 = blockIdx.y * 128;
    const int n0 = blockIdx.x * 256;

    // cp.async staging: 512 threads, 3 cp16 each.
    //   A: chunk tid        -> row tid>>2 (0..127),  16B col (tid&3)
    //   B: chunks tid, tid+512 -> rows tid>>2, 128+(tid>>2)
    const int srow = tid >> 2;            // 0..127
    const int sc16 = (tid & 3) * 8;       // half offset 0,8,16,24

    const __half* gA  = A  + (size_t)(m0 + srow) * K + sc16;
    const __half* gB0 = Bw + (size_t)(n0 + srow) * K + sc16;
    const __half* gB1 = Bw + (size_t)(n0 + 128 + srow) * K + sc16;

    const uint32_t dAoff  = (uint32_t)(srow * SHH + sc16) * 2;
    const uint32_t dB0off = dAoff;
    const uint32_t dB1off = (uint32_t)((srow + 128) * SHH + sc16) * 2;

    // ldmatrix lane offsets (bytes)
    const uint32_t laneA = ((lane & 15) * SHH + (lane >> 4) * 8) * 2;
    const uint32_t laneB = (((lane & 7) + ((lane >> 4) << 3)) * SHH +
                            ((lane >> 3) & 1) * 8) * 2;

    float acc[2][8][4];
#pragma unroll
    for (int i = 0; i < 2; i++)
#pragma unroll
        for (int j = 0; j < 8; j++)
#pragma unroll
            for (int r = 0; r < 4; r++) acc[i][j][r] = 0.f;

    auto aBase = [&](int st) { return sbase + st * A_STAGE; };
    auto bBase = [&](int st) { return sbase + NSTAGE * A_STAGE + st * B_STAGE; };

    auto load_stage = [&](int st, int k0) {
        cp16(aBase(st) + dAoff,  gA  + k0);
        cp16(bBase(st) + dB0off, gB0 + k0);
        cp16(bBase(st) + dB1off, gB1 + k0);
    };

    const int NIT = K >> 5;
    load_stage(0, 0);
    asm volatile("cp.async.commit_group;\n" ::: "memory");
    load_stage(1, 32);
    asm volatile("cp.async.commit_group;\n" ::: "memory");

    for (int it = 0; it < NIT; ++it) {
        const int cur = it % NSTAGE;
        if (it < NIT - 1) {
            asm volatile("cp.async.wait_group 1;\n" ::: "memory");
        } else {
            asm volatile("cp.async.wait_group 0;\n" ::: "memory");
        }
        __syncthreads();

        if (it + 2 < NIT) {
            load_stage((it + 2) % NSTAGE, (it + 2) << 5);
            asm volatile("cp.async.commit_group;\n" ::: "memory");
        }

        const uint32_t aSt = aBase(cur);
        const uint32_t bSt = bBase(cur);
#pragma unroll
        for (int ks = 0; ks < 2; ks++) {
            uint32_t afr[2][4];
#pragma unroll
            for (int mt = 0; mt < 2; mt++)
                ldsm4(afr[mt], aSt + (wm * 32 + mt * 16) * (SHH * 2) + ks * 32 + laneA);
            uint32_t bfr[4][4];
#pragma unroll
            for (int np = 0; np < 4; np++)
                ldsm4(bfr[np], bSt + (wn * 64 + np * 16) * (SHH * 2) + ks * 32 + laneB);
#pragma unroll
            for (int mt = 0; mt < 2; mt++)
#pragma unroll
                for (int nt = 0; nt < 8; nt++)
                    mma_f16(acc[mt][nt], afr[mt], &bfr[nt >> 1][(nt & 1) * 2]);
        }
    }
    __syncthreads();

#pragma unroll
    for (int mt = 0; mt < 2; mt++) {
        const int row = m0 + wm * 32 + mt * 16 + grp;
#pragma unroll
        for (int nt = 0; nt < 8; nt++) {
            const int col = n0 + wn * 64 + nt * 8 + tig * 2;
            *reinterpret_cast<float2*>(&C[(size_t)row * ldc + col]) =
                make_float2(acc[mt][nt][0], acc[mt][nt][1]);
            *reinterpret_cast<float2*>(&C[(size_t)(row + 8) * ldc + col]) =
                make_float2(acc[mt][nt][2], acc[mt][nt][3]);
        }
    }
}

// ---------------------------------------------------------------------------
// K1b: skinny fp32 GEMM for the 16 "w" columns (exact fp32).
// ---------------------------------------------------------------------------
__global__ __launch_bounds__(256)
void wgemm_kernel(const float* __restrict__ x, const float* __restrict__ ipw)
{
    __shared__ float Xs[128][65];
    __shared__ float Ws[16][64];

    const int tid = threadIdx.x;
    const int col = tid & 15;
    const int rg  = tid >> 4;
    const int m0  = blockIdx.x * 128;

    float acc[8];
#pragma unroll
    for (int r = 0; r < 8; r++) acc[r] = 0.f;

    for (int k0 = 0; k0 < DM_; k0 += 64) {
        {
            const int row = tid >> 1;
            const int kk0 = (tid & 1) * 32;
#pragma unroll
            for (int q = 0; q < 8; q++) {
                float4 v = *reinterpret_cast<const float4*>(
                    &x[(size_t)(m0 + row) * DM_ + k0 + kk0 + q * 4]);
                Xs[row][kk0 + q * 4 + 0] = v.x;
                Xs[row][kk0 + q * 4 + 1] = v.y;
                Xs[row][kk0 + q * 4 + 2] = v.z;
                Xs[row][kk0 + q * 4 + 3] = v.w;
            }
        }
        {
            const int wr = tid >> 4;
            const int wk = (tid & 15) * 4;
            if (wr < 16) {
                float4 v = *reinterpret_cast<const float4*>(
                    &ipw[(size_t)(1024 + wr) * DM_ + k0 + wk]);
                Ws[wr][wk + 0] = v.x;
                Ws[wr][wk + 1] = v.y;
                Ws[wr][wk + 2] = v.z;
                Ws[wr][wk + 3] = v.w;
            }
        }
        __syncthreads();

#pragma unroll 8
        for (int k = 0; k < 64; k++) {
            const float wv = Ws[col][k];
#pragma unroll
            for (int r = 0; r < 8; r++)
                acc[r] = fmaf(Xs[rg + r * 16][k], wv, acc[r]);
        }
        __syncthreads();
    }

#pragma unroll
    for (int r = 0; r < 8; r++)
        g_xw[(size_t)(m0 + rg + r * 16) * E_ + 1024 + col] = acc[r];
}

// ---------------------------------------------------------------------------
// K2: per-(b,h,c) chunk stats — rolling conv window.
// ---------------------------------------------------------------------------
__global__ __launch_bounds__(64)
void chunk_stats_kernel(const float* __restrict__ conv_w,
                        const float* __restrict__ conv_b,
                        const float* __restrict__ w_base)
{
    const int c = blockIdx.x, h = blockIdx.y, b = blockIdx.z;
    const int n = threadIdx.x;

    __shared__ float sS[64];
    __shared__ float sE[64];
    __shared__ float sMin;

    const int ch = h * 64 + n;
    const float cw0 = conv_w[ch * 4 + 0];
    const float cw1 = conv_w[ch * 4 + 1];
    const float cw2 = conv_w[ch * 4 + 2];
    const float cw3 = conv_w[ch * 4 + 3];
    const float cb  = conv_b[ch];

    const int s0 = c * 64;
    const float* xwb = g_xw + (size_t)b * S_ * E_;
    const float* xp  = xwb + (size_t)s0 * E_ + h * 64 + n;

    float xm3 = 0.f, xm2 = 0.f, xm1 = 0.f;
    if (c > 0) {
        xm3 = xp[-(ptrdiff_t)(3 * E_)];
        xm2 = xp[-(ptrdiff_t)(2 * E_)];
        xm1 = xp[-(ptrdiff_t)(1 * E_)];
    }

    sS[n] = xwb[(size_t)(s0 + n) * E_ + 1024 + h] * w_base[h];
    __syncthreads();

    if (n == 0) {
        float run = 0.f, mn = 3.4e38f;
        for (int i = 0; i < 64; i++) {
            run += sS[i];
            sS[i] = run;
            mn = fminf(mn, run);
        }
        sMin = mn;
    }
    __syncthreads();
    sE[n] = __expf(-sS[n]);
    __syncthreads();

    float r = 0.f, rn = 0.f;
#pragma unroll 4
    for (int i = 0; i < 64; i++) {
        const float x0 = xp[(size_t)i * E_];
        const float xv = cb + cw0 * xm3 + cw1 * xm2 + cw2 * xm1 + cw3 * x0;
        xm3 = xm2; xm2 = xm1; xm1 = x0;
        const float e = sE[i];
        r  = fmaf(e, xv, r);
        rn += e;
    }

    const float sc  = __expf(sMin);
    const int   idx = (b * H_ + h) * C_ + c;
    g_states[idx * N_ + n] = sc * r;
    if (n == 0) {
        g_cnorm[idx] = sc * rn;
        g_T[idx]     = sS[63];
    }
}

// ---------------------------------------------------------------------------
// K3: per-(b,h) cross-chunk scan — 256 threads.
// ---------------------------------------------------------------------------
__global__ __launch_bounds__(256)
void chunk_scan_kernel()
{
    const int h = blockIdx.x, b = blockIdx.y;
    const int tid = threadIdx.x;
    const int n  = tid & 63;
    const int zq = tid >> 6;

    __shared__ float G[65];
    __shared__ float MP[64];
    __shared__ float W[64][64];
    __shared__ float st[64][64];
    __shared__ float cn[64];

    const int base = (b * H_ + h) * C_;

    for (int idx = tid; idx < 4096; idx += 256)
        st[idx >> 6][idx & 63] = g_states[(size_t)base * N_ + idx];
    if (tid < 64) cn[tid] = g_cnorm[base + tid];
    __syncthreads();

    if (tid == 0) {
        float run = 0.f;
        G[0] = 0.f;
        for (int c = 0; c < 64; c++) { run += g_T[base + c]; G[c + 1] = run; }
        float mn = 3.4e38f;
        for (int z = 0; z < 64; z++) { mn = fminf(mn, G[z]); MP[z] = mn; }
    }
    __syncthreads();

    for (int idx = tid; idx < 4096; idx += 256) {
        const int z = idx >> 6, cp = idx & 63;
        W[z][cp] = (cp < z) ? __expf(MP[z] - G[cp + 1]) : 0.f;
    }
    __syncthreads();

    for (int z = zq; z < 64; z += 4) {
        float accv = 0.f;
        for (int cp = 0; cp < z; cp++) accv = fmaf(W[z][cp], st[cp][n], accv);
        g_nstates[(base + z) * N_ + n] = accv;
    }
    if (tid < 64) {
        float accn = 0.f;
        for (int cp = 0; cp < tid; cp++) accn = fmaf(W[tid][cp], cn[cp], accn);
        g_nnorm[base + tid] = accn;
    }
}

// ---------------------------------------------------------------------------
// K4: per-(b,h,c) combine -> y (written as fp16 for GEMM2).
// ---------------------------------------------------------------------------
__global__ __launch_bounds__(64)
void combine_kernel(const float* __restrict__ conv_w,
                    const float* __restrict__ conv_b,
                    const float* __restrict__ w_base)
{
    const int c = blockIdx.x, h = blockIdx.y, b = blockIdx.z;
    const int n = threadIdx.x;

    __shared__ float sS[64];
    __shared__ float sE[64], sEMP[64], sSDO[64];
    __shared__ float sMP[64];
    __shared__ float sMax;

    const int ch = h * 64 + n;
    const float cw0 = conv_w[ch * 4 + 0];
    const float cw1 = conv_w[ch * 4 + 1];
    const float cw2 = conv_w[ch * 4 + 2];
    const float cw3 = conv_w[ch * 4 + 3];
    const float cb  = conv_b[ch];

    const int s0 = c * 64;
    const float* xwb = g_xw + (size_t)b * S_ * E_;
    const float* xp  = xwb + (size_t)s0 * E_ + h * 64 + n;

    float xm3 = 0.f, xm2 = 0.f, xm1 = 0.f;
    if (c > 0) {
        xm3 = xp[-(ptrdiff_t)(3 * E_)];
        xm2 = xp[-(ptrdiff_t)(2 * E_)];
        xm1 = xp[-(ptrdiff_t)(1 * E_)];
    }

    sS[n] = xwb[(size_t)(s0 + n) * E_ + 1024 + h] * w_base[h];
    __syncthreads();

    if (n == 0) {
        float run = 0.f, mn = 3.4e38f, mx = -3.4e38f;
        for (int i = 0; i < 64; i++) {
            run += sS[i];
            sS[i] = run;
            mn = fminf(mn, run);
            sMP[i] = mn;
            mx = fmaxf(mx, run);
        }
        sMax = mx;
    }
    __syncthreads();
    sE[n]   = __expf(-sS[n]);
    sEMP[n] = __expf(sMP[n]);
    sSDO[n] = __expf(sS[n] - sMax);
    __syncthreads();

    const int idx = (b * H_ + h) * C_ + c;
    const float ns = g_nstates[idx * N_ + n];
    const float nn = g_nnorm[idx];

    float r = 0.f, rn = 0.f;
    __half* yout = g_yh + (size_t)(b * S_ + s0) * DM_ + h * 64 + n;

#pragma unroll 4
    for (int i = 0; i < 64; i++) {
        const float x0 = xp[(size_t)i * E_];
        const float xv = cb + cw0 * xm3 + cw1 * xm2 + cw2 * xm1 + cw3 * x0;
        xm3 = xm2; xm2 = xm1; xm1 = x0;
        const float e = sE[i];
        r  = fmaf(e, xv, r);
        rn += e;
        const float emp = sEMP[i];
        const float sdo = sSDO[i];
        const float num = fmaf(sdo, ns, emp * r);
        const float den = fmaf(sdo, nn, emp * rn);
        yout[(size_t)i * DM_] = __float2half_rn(num / den);
    }
}

// ---------------------------------------------------------------------------
// Launch
// ---------------------------------------------------------------------------
extern "C" void kernel_launch(void* const* d_in, const int* in_sizes, int n_in,
                              void* d_out, int out_size)
{
    const float *x = nullptr, *ipw = nullptr, *cw = nullptr,
                *cb = nullptr, *wb = nullptr, *opw = nullptr;
    for (int i = 0; i < n_in; i++) {
        switch (in_sizes[i]) {
            case M_ * DM_:  x   = (const float*)d_in[i]; break;
            case E_ * DM_:  ipw = (const float*)d_in[i]; break;
            case DM_ * 4:   cw  = (const float*)d_in[i]; break;
            case DM_:       cb  = (const float*)d_in[i]; break;
            case H_:        wb  = (const float*)d_in[i]; break;
            case DM_ * DM_: opw = (const float*)d_in[i]; break;
        }
    }

    __half *xh, *ipwh, *opwh;
    cudaGetSymbolAddress((void**)&xh,   g_xh);
    cudaGetSymbolAddress((void**)&ipwh, g_ipwh);
    cudaGetSymbolAddress((void**)&opwh, g_opwh);

    static bool attr_done = false;
    if (!attr_done) {
        cudaFuncSetAttribute(hgemm_tc<true>,
                             cudaFuncAttributeMaxDynamicSharedMemorySize, GEMM_SMEM);
        cudaFuncSetAttribute(hgemm_tc<false>,
                             cudaFuncAttributeMaxDynamicSharedMemorySize, GEMM_SMEM);
        attr_done = true;
    }

    // C0: fp32 -> fp16 operand conversion
    f2h_kernel<<<4096, 256>>>(x, xh, M_ * DM_ / 4);
    f2h_kernel<<<512, 256>>>(ipw, ipwh, DM_ * DM_ / 4);   // first 1024 rows only
    f2h_kernel<<<512, 256>>>(opw, opwh, DM_ * DM_ / 4);

    // K1a: xi = x @ in_proj_w[:1024]^T (fp16 TC, 128x256 tile, 512 thr)
    hgemm_tc<true><<<dim3(DM_ / 256, M_ / 128), 512, GEMM_SMEM>>>(nullptr, DM_, E_);

    // K1b: w = x @ in_proj_w[1024:]^T (fp32 exact)
    wgemm_kernel<<<M_ / 128, 256>>>(x, ipw);

    // K2: per-chunk stats
    chunk_stats_kernel<<<dim3(C_, H_, B_), 64>>>(cw, cb, wb);

    // K3: cross-chunk scan
    chunk_scan_kernel<<<dim3(H_, B_), 256>>>();

    // K4: combine -> y (fp16)
    combine_kernel<<<dim3(C_, H_, B_), 64>>>(cw, cb, wb);

    // K5: out = y @ out_proj_w^T (fp16 TC, 128x256 tile, 512 thr)
    hgemm_tc<false><<<dim3(DM_ / 256, M_ / 128), 512, GEMM_SMEM>>>(
        (float*)d_out, DM_, DM_);
}

// round 9
// speedup vs baseline: 1.7290x; 1.0329x over previous
#include <cuda_runtime.h>
#include <cuda_fp16.h>
#include <cstdint>
#include <cstddef>

// ---------------------------------------------------------------------------
// DecayBlock (Mamba-2 SSD block) — round 9:
//   * GEMM: BK 32 -> 64 per stage (3 stages, 162 KB smem): half the barriers,
//     2x longer runway between syncs for latency overlap.
//   * wgemm fused with x fp32->fp16 conversion (drops standalone f2h pass).
// ---------------------------------------------------------------------------

namespace {
constexpr int B_  = 8;
constexpr int S_  = 4096;
constexpr int DM_ = 1024;
constexpr int H_  = 16;
constexpr int N_  = 64;
constexpr int C_  = 64;
constexpr int E_  = 1040;
constexpr int M_  = B_ * S_;
constexpr int SHH = 72;                    // smem row stride (64 halves + 8 pad)
constexpr int A_STAGE = 128 * SHH * 2;     // 18432 B
constexpr int B_STAGE = 256 * SHH * 2;     // 36864 B
constexpr int NSTAGE  = 3;
constexpr int GEMM_SMEM = NSTAGE * (A_STAGE + B_STAGE);   // 165888 B
}

// Scratch (allocation-free: __device__ globals)
__device__ __align__(16) float  g_xw[(size_t)M_ * E_];
__device__ __align__(16) __half g_xh[(size_t)M_ * DM_];
__device__ __align__(16) __half g_yh[(size_t)M_ * DM_];
__device__ __align__(16) __half g_ipwh[(size_t)DM_ * DM_];
__device__ __align__(16) __half g_opwh[(size_t)DM_ * DM_];
__device__ __align__(16) float g_states[B_ * H_ * C_ * N_];
__device__ float g_cnorm[B_ * H_ * C_];
__device__ float g_T[B_ * H_ * C_];
__device__ __align__(16) float g_nstates[B_ * H_ * C_ * N_];
__device__ float g_nnorm[B_ * H_ * C_];

__device__ __forceinline__ uint32_t pk(float lo, float hi) {
    __half2 h = __floats2half2_rn(lo, hi);
    return *reinterpret_cast<uint32_t*>(&h);
}

__device__ __forceinline__ void mma_f16(float* c, const uint32_t* a, const uint32_t* b) {
    asm volatile(
        "mma.sync.aligned.m16n8k16.row.col.f32.f16.f16.f32 "
        "{%0,%1,%2,%3}, {%4,%5,%6,%7}, {%8,%9}, {%0,%1,%2,%3};\n"
        : "+f"(c[0]), "+f"(c[1]), "+f"(c[2]), "+f"(c[3])
        : "r"(a[0]), "r"(a[1]), "r"(a[2]), "r"(a[3]), "r"(b[0]), "r"(b[1]));
}

__device__ __forceinline__ void cp16(uint32_t smem, const void* gmem) {
    asm volatile("cp.async.cg.shared.global [%0], [%1], 16;\n" :: "r"(smem), "l"(gmem));
}

__device__ __forceinline__ void ldsm4(uint32_t* r, uint32_t addr) {
    asm volatile("ldmatrix.sync.aligned.m8n8.x4.shared.b16 {%0,%1,%2,%3}, [%4];"
                 : "=r"(r[0]), "=r"(r[1]), "=r"(r[2]), "=r"(r[3]) : "r"(addr));
}

// ---------------------------------------------------------------------------
// fp32 -> fp16 conversion (grid-stride over float4s) — weights only now
// ---------------------------------------------------------------------------
__global__ __launch_bounds__(256)
void f2h_kernel(const float* __restrict__ src, __half* __restrict__ dst, int n4)
{
    for (int i = blockIdx.x * blockDim.x + threadIdx.x; i < n4;
         i += gridDim.x * blockDim.x) {
        float4 v = reinterpret_cast<const float4*>(src)[i];
        uint2 u = make_uint2(pk(v.x, v.y), pk(v.z, v.w));
        reinterpret_cast<uint2*>(dst)[i] = u;
    }
}

// ---------------------------------------------------------------------------
// FP16 tensor GEMM (NT): C[M,N] = A[M,K] * B[N,K]^T, A/B fp16, C fp32.
// Block tile 128x256, 512 threads = 16 warps (4m x 4n), warp tile 32x64,
// BK=64 per stage, 3-stage cp.async ring, ldmatrix.x4, mma m16n8k16.
// ---------------------------------------------------------------------------
template <bool FIRST>
__global__ __launch_bounds__(512)
void hgemm_tc(float* __restrict__ Carg, int K, int ldc)
{
    const __half* A  = FIRST ? g_xh   : g_yh;
    const __half* Bw = FIRST ? g_ipwh : g_opwh;
    float*        C  = FIRST ? g_xw   : Carg;

    extern __shared__ __align__(16) char smem[];
    const uint32_t sbase = (uint32_t)__cvta_generic_to_shared(smem);

    const int tid  = threadIdx.x;
    const int lane = tid & 31;
    const int warp = tid >> 5;
    const int wm   = warp & 3;        // m offset wm*32
    const int wn   = warp >> 2;       // n offset wn*64
    const int grp  = lane >> 2;
    const int tig  = lane & 3;

    const int m0 = blockIdx.y * 128;
    const int n0 = blockIdx.x * 256;

    // cp.async staging for BK=64: thread -> row tid>>2, 16-half col group
    const int srow = tid >> 2;            // 0..127
    const int sc16 = (tid & 3) * 16;      // half offset 0,16,32,48

    const __half* gA  = A  + (size_t)(m0 + srow) * K + sc16;
    const __half* gB0 = Bw + (size_t)(n0 + srow) * K + sc16;
    const __half* gB1 = Bw + (size_t)(n0 + 128 + srow) * K + sc16;

    const uint32_t dAoff  = (uint32_t)(srow * SHH + sc16) * 2;
    const uint32_t dB0off = dAoff;
    const uint32_t dB1off = (uint32_t)((srow + 128) * SHH + sc16) * 2;

    // ldmatrix lane offsets (bytes) within a 16-k window
    const uint32_t laneA = ((lane & 15) * SHH + (lane >> 4) * 8) * 2;
    const uint32_t laneB = (((lane & 7) + ((lane >> 4) << 3)) * SHH +
                            ((lane >> 3) & 1) * 8) * 2;

    float acc[2][8][4];
#pragma unroll
    for (int i = 0; i < 2; i++)
#pragma unroll
        for (int j = 0; j < 8; j++)
#pragma unroll
            for (int r = 0; r < 4; r++) acc[i][j][r] = 0.f;

    auto aBase = [&](int st) { return sbase + st * A_STAGE; };
    auto bBase = [&](int st) { return sbase + NSTAGE * A_STAGE + st * B_STAGE; };

    auto load_stage = [&](int st, int k0) {
        cp16(aBase(st) + dAoff,       gA  + k0);
        cp16(aBase(st) + dAoff + 16,  gA  + k0 + 8);
        cp16(bBase(st) + dB0off,      gB0 + k0);
        cp16(bBase(st) + dB0off + 16, gB0 + k0 + 8);
        cp16(bBase(st) + dB1off,      gB1 + k0);
        cp16(bBase(st) + dB1off + 16, gB1 + k0 + 8);
    };

    const int NIT = K >> 6;   // BK=64
    load_stage(0, 0);
    asm volatile("cp.async.commit_group;\n" ::: "memory");
    load_stage(1, 64);
    asm volatile("cp.async.commit_group;\n" ::: "memory");

    for (int it = 0; it < NIT; ++it) {
        const int cur = it % NSTAGE;
        if (it < NIT - 1) {
            asm volatile("cp.async.wait_group 1;\n" ::: "memory");
        } else {
            asm volatile("cp.async.wait_group 0;\n" ::: "memory");
        }
        __syncthreads();

        if (it + 2 < NIT) {
            load_stage((it + 2) % NSTAGE, (it + 2) << 6);
            asm volatile("cp.async.commit_group;\n" ::: "memory");
        }

        const uint32_t aSt = aBase(cur);
        const uint32_t bSt = bBase(cur);
#pragma unroll
        for (int ks = 0; ks < 4; ks++) {
            uint32_t afr[2][4];
#pragma unroll
            for (int mt = 0; mt < 2; mt++)
                ldsm4(afr[mt], aSt + (wm * 32 + mt * 16) * (SHH * 2) + ks * 32 + laneA);
            uint32_t bfr[4][4];
#pragma unroll
            for (int np = 0; np < 4; np++)
                ldsm4(bfr[np], bSt + (wn * 64 + np * 16) * (SHH * 2) + ks * 32 + laneB);
#pragma unroll
            for (int mt = 0; mt < 2; mt++)
#pragma unroll
                for (int nt = 0; nt < 8; nt++)
                    mma_f16(acc[mt][nt], afr[mt], &bfr[nt >> 1][(nt & 1) * 2]);
        }
    }
    __syncthreads();

#pragma unroll
    for (int mt = 0; mt < 2; mt++) {
        const int row = m0 + wm * 32 + mt * 16 + grp;
#pragma unroll
        for (int nt = 0; nt < 8; nt++) {
            const int col = n0 + wn * 64 + nt * 8 + tig * 2;
            *reinterpret_cast<float2*>(&C[(size_t)row * ldc + col]) =
                make_float2(acc[mt][nt][0], acc[mt][nt][1]);
            *reinterpret_cast<float2*>(&C[(size_t)(row + 8) * ldc + col]) =
                make_float2(acc[mt][nt][2], acc[mt][nt][3]);
        }
    }
}

// ---------------------------------------------------------------------------
// K1b: skinny fp32 GEMM for the 16 "w" columns (exact fp32), FUSED with
// the x fp32->fp16 conversion (this kernel already streams all of x).
// ---------------------------------------------------------------------------
__global__ __launch_bounds__(256)
void wgemm_kernel(const float* __restrict__ x, const float* __restrict__ ipw)
{
    __shared__ float Xs[128][65];
    __shared__ float Ws[16][64];

    const int tid = threadIdx.x;
    const int col = tid & 15;
    const int rg  = tid >> 4;
    const int m0  = blockIdx.x * 128;

    float acc[8];
#pragma unroll
    for (int r = 0; r < 8; r++) acc[r] = 0.f;

    for (int k0 = 0; k0 < DM_; k0 += 64) {
        {
            const int row = tid >> 1;
            const int kk0 = (tid & 1) * 32;
            __half* xh_row = g_xh + (size_t)(m0 + row) * DM_ + k0 + kk0;
#pragma unroll
            for (int q = 0; q < 8; q++) {
                float4 v = *reinterpret_cast<const float4*>(
                    &x[(size_t)(m0 + row) * DM_ + k0 + kk0 + q * 4]);
                Xs[row][kk0 + q * 4 + 0] = v.x;
                Xs[row][kk0 + q * 4 + 1] = v.y;
                Xs[row][kk0 + q * 4 + 2] = v.z;
                Xs[row][kk0 + q * 4 + 3] = v.w;
                // fused fp16 emit
                *reinterpret_cast<uint2*>(xh_row + q * 4) =
                    make_uint2(pk(v.x, v.y), pk(v.z, v.w));
            }
        }
        {
            const int wr = tid >> 4;
            const int wk = (tid & 15) * 4;
            if (wr < 16) {
                float4 v = *reinterpret_cast<const float4*>(
                    &ipw[(size_t)(1024 + wr) * DM_ + k0 + wk]);
                Ws[wr][wk + 0] = v.x;
                Ws[wr][wk + 1] = v.y;
                Ws[wr][wk + 2] = v.z;
                Ws[wr][wk + 3] = v.w;
            }
        }
        __syncthreads();

#pragma unroll 8
        for (int k = 0; k < 64; k++) {
            const float wv = Ws[col][k];
#pragma unroll
            for (int r = 0; r < 8; r++)
                acc[r] = fmaf(Xs[rg + r * 16][k], wv, acc[r]);
        }
        __syncthreads();
    }

#pragma unroll
    for (int r = 0; r < 8; r++)
        g_xw[(size_t)(m0 + rg + r * 16) * E_ + 1024 + col] = acc[r];
}

// ---------------------------------------------------------------------------
// K2: per-(b,h,c) chunk stats — rolling conv window.
// ---------------------------------------------------------------------------
__global__ __launch_bounds__(64)
void chunk_stats_kernel(const float* __restrict__ conv_w,
                        const float* __restrict__ conv_b,
                        const float* __restrict__ w_base)
{
    const int c = blockIdx.x, h = blockIdx.y, b = blockIdx.z;
    const int n = threadIdx.x;

    __shared__ float sS[64];
    __shared__ float sE[64];
    __shared__ float sMin;

    const int ch = h * 64 + n;
    const float cw0 = conv_w[ch * 4 + 0];
    const float cw1 = conv_w[ch * 4 + 1];
    const float cw2 = conv_w[ch * 4 + 2];
    const float cw3 = conv_w[ch * 4 + 3];
    const float cb  = conv_b[ch];

    const int s0 = c * 64;
    const float* xwb = g_xw + (size_t)b * S_ * E_;
    const float* xp  = xwb + (size_t)s0 * E_ + h * 64 + n;

    float xm3 = 0.f, xm2 = 0.f, xm1 = 0.f;
    if (c > 0) {
        xm3 = xp[-(ptrdiff_t)(3 * E_)];
        xm2 = xp[-(ptrdiff_t)(2 * E_)];
        xm1 = xp[-(ptrdiff_t)(1 * E_)];
    }

    sS[n] = xwb[(size_t)(s0 + n) * E_ + 1024 + h] * w_base[h];
    __syncthreads();

    if (n == 0) {
        float run = 0.f, mn = 3.4e38f;
        for (int i = 0; i < 64; i++) {
            run += sS[i];
            sS[i] = run;
            mn = fminf(mn, run);
        }
        sMin = mn;
    }
    __syncthreads();
    sE[n] = __expf(-sS[n]);
    __syncthreads();

    float r = 0.f, rn = 0.f;
#pragma unroll 4
    for (int i = 0; i < 64; i++) {
        const float x0 = xp[(size_t)i * E_];
        const float xv = cb + cw0 * xm3 + cw1 * xm2 + cw2 * xm1 + cw3 * x0;
        xm3 = xm2; xm2 = xm1; xm1 = x0;
        const float e = sE[i];
        r  = fmaf(e, xv, r);
        rn += e;
    }

    const float sc  = __expf(sMin);
    const int   idx = (b * H_ + h) * C_ + c;
    g_states[idx * N_ + n] = sc * r;
    if (n == 0) {
        g_cnorm[idx] = sc * rn;
        g_T[idx]     = sS[63];
    }
}

// ---------------------------------------------------------------------------
// K3: per-(b,h) cross-chunk scan — 256 threads.
// ---------------------------------------------------------------------------
__global__ __launch_bounds__(256)
void chunk_scan_kernel()
{
    const int h = blockIdx.x, b = blockIdx.y;
    const int tid = threadIdx.x;
    const int n  = tid & 63;
    const int zq = tid >> 6;

    __shared__ float G[65];
    __shared__ float MP[64];
    __shared__ float W[64][64];
    __shared__ float st[64][64];
    __shared__ float cn[64];

    const int base = (b * H_ + h) * C_;

    for (int idx = tid; idx < 4096; idx += 256)
        st[idx >> 6][idx & 63] = g_states[(size_t)base * N_ + idx];
    if (tid < 64) cn[tid] = g_cnorm[base + tid];
    __syncthreads();

    if (tid == 0) {
        float run = 0.f;
        G[0] = 0.f;
        for (int c = 0; c < 64; c++) { run += g_T[base + c]; G[c + 1] = run; }
        float mn = 3.4e38f;
        for (int z = 0; z < 64; z++) { mn = fminf(mn, G[z]); MP[z] = mn; }
    }
    __syncthreads();

    for (int idx = tid; idx < 4096; idx += 256) {
        const int z = idx >> 6, cp = idx & 63;
        W[z][cp] = (cp < z) ? __expf(MP[z] - G[cp + 1]) : 0.f;
    }
    __syncthreads();

    for (int z = zq; z < 64; z += 4) {
        float accv = 0.f;
        for (int cp = 0; cp < z; cp++) accv = fmaf(W[z][cp], st[cp][n], accv);
        g_nstates[(base + z) * N_ + n] = accv;
    }
    if (tid < 64) {
        float accn = 0.f;
        for (int cp = 0; cp < tid; cp++) accn = fmaf(W[tid][cp], cn[cp], accn);
        g_nnorm[base + tid] = accn;
    }
}

// ---------------------------------------------------------------------------
// K4: per-(b,h,c) combine -> y (written as fp16 for GEMM2).
// ---------------------------------------------------------------------------
__global__ __launch_bounds__(64)
void combine_kernel(const float* __restrict__ conv_w,
                    const float* __restrict__ conv_b,
                    const float* __restrict__ w_base)
{
    const int c = blockIdx.x, h = blockIdx.y, b = blockIdx.z;
    const int n = threadIdx.x;

    __shared__ float sS[64];
    __shared__ float sE[64], sEMP[64], sSDO[64];
    __shared__ float sMP[64];
    __shared__ float sMax;

    const int ch = h * 64 + n;
    const float cw0 = conv_w[ch * 4 + 0];
    const float cw1 = conv_w[ch * 4 + 1];
    const float cw2 = conv_w[ch * 4 + 2];
    const float cw3 = conv_w[ch * 4 + 3];
    const float cb  = conv_b[ch];

    const int s0 = c * 64;
    const float* xwb = g_xw + (size_t)b * S_ * E_;
    const float* xp  = xwb + (size_t)s0 * E_ + h * 64 + n;

    float xm3 = 0.f, xm2 = 0.f, xm1 = 0.f;
    if (c > 0) {
        xm3 = xp[-(ptrdiff_t)(3 * E_)];
        xm2 = xp[-(ptrdiff_t)(2 * E_)];
        xm1 = xp[-(ptrdiff_t)(1 * E_)];
    }

    sS[n] = xwb[(size_t)(s0 + n) * E_ + 1024 + h] * w_base[h];
    __syncthreads();

    if (n == 0) {
        float run = 0.f, mn = 3.4e38f, mx = -3.4e38f;
        for (int i = 0; i < 64; i++) {
            run += sS[i];
            sS[i] = run;
            mn = fminf(mn, run);
            sMP[i] = mn;
            mx = fmaxf(mx, run);
        }
        sMax = mx;
    }
    __syncthreads();
    sE[n]   = __expf(-sS[n]);
    sEMP[n] = __expf(sMP[n]);
    sSDO[n] = __expf(sS[n] - sMax);
    __syncthreads();

    const int idx = (b * H_ + h) * C_ + c;
    const float ns = g_nstates[idx * N_ + n];
    const float nn = g_nnorm[idx];

    float r = 0.f, rn = 0.f;
    __half* yout = g_yh + (size_t)(b * S_ + s0) * DM_ + h * 64 + n;

#pragma unroll 4
    for (int i = 0; i < 64; i++) {
        const float x0 = xp[(size_t)i * E_];
        const float xv = cb + cw0 * xm3 + cw1 * xm2 + cw2 * xm1 + cw3 * x0;
        xm3 = xm2; xm2 = xm1; xm1 = x0;
        const float e = sE[i];
        r  = fmaf(e, xv, r);
        rn += e;
        const float emp = sEMP[i];
        const float sdo = sSDO[i];
        const float num = fmaf(sdo, ns, emp * r);
        const float den = fmaf(sdo, nn, emp * rn);
        yout[(size_t)i * DM_] = __float2half_rn(num / den);
    }
}

// ---------------------------------------------------------------------------
// Launch
// ---------------------------------------------------------------------------
extern "C" void kernel_launch(void* const* d_in, const int* in_sizes, int n_in,
                              void* d_out, int out_size)
{
    const float *x = nullptr, *ipw = nullptr, *cw = nullptr,
                *cb = nullptr, *wb = nullptr, *opw = nullptr;
    for (int i = 0; i < n_in; i++) {
        switch (in_sizes[i]) {
            case M_ * DM_:  x   = (const float*)d_in[i]; break;
            case E_ * DM_:  ipw = (const float*)d_in[i]; break;
            case DM_ * 4:   cw  = (const float*)d_in[i]; break;
            case DM_:       cb  = (const float*)d_in[i]; break;
            case H_:        wb  = (const float*)d_in[i]; break;
            case DM_ * DM_: opw = (const float*)d_in[i]; break;
        }
    }

    __half *ipwh, *opwh;
    cudaGetSymbolAddress((void**)&ipwh, g_ipwh);
    cudaGetSymbolAddress((void**)&opwh, g_opwh);

    static bool attr_done = false;
    if (!attr_done) {
        cudaFuncSetAttribute(hgemm_tc<true>,
                             cudaFuncAttributeMaxDynamicSharedMemorySize, GEMM_SMEM);
        cudaFuncSetAttribute(hgemm_tc<false>,
                             cudaFuncAttributeMaxDynamicSharedMemorySize, GEMM_SMEM);
        attr_done = true;
    }

    // C0: weight fp32 -> fp16 conversion
    f2h_kernel<<<512, 256>>>(ipw, ipwh, DM_ * DM_ / 4);   // first 1024 rows only
    f2h_kernel<<<512, 256>>>(opw, opwh, DM_ * DM_ / 4);

    // K1b: w = x @ in_proj_w[1024:]^T (fp32 exact) + emits x as fp16
    wgemm_kernel<<<M_ / 128, 256>>>(x, ipw);

    // K1a: xi = x @ in_proj_w[:1024]^T (fp16 TC, 128x256, BK=64, 512 thr)
    hgemm_tc<true><<<dim3(DM_ / 256, M_ / 128), 512, GEMM_SMEM>>>(nullptr, DM_, E_);

    // K2: per-chunk stats
    chunk_stats_kernel<<<dim3(C_, H_, B_), 64>>>(cw, cb, wb);

    // K3: cross-chunk scan
    chunk_scan_kernel<<<dim3(H_, B_), 256>>>();

    // K4: combine -> y (fp16)
    combine_kernel<<<dim3(C_, H_, B_), 64>>>(cw, cb, wb);

    // K5: out = y @ out_proj_w^T (fp16 TC, 128x256, BK=64, 512 thr)
    hgemm_tc<false><<<dim3(DM_ / 256, M_ / 128), 512, GEMM_SMEM>>>(
        (float*)d_out, DM_, DM_);
}

// round 10
// speedup vs baseline: 1.8032x; 1.0429x over previous
#include <cuda_runtime.h>
#include <cuda_fp16.h>
#include <cstdint>
#include <cstddef>

// ---------------------------------------------------------------------------
// DecayBlock (Mamba-2 SSD block) — round 10:
//   * hgemm: ldmatrix fragment double-buffering (hide LDSM under MMA)
//   * wgemm: 512-thr, W fully smem-resident, float4 paths, single wave
//   * stats/combine: 4 chunks per block; weight f2h merged to one launch
// ---------------------------------------------------------------------------

namespace {
constexpr int B_  = 8;
constexpr int S_  = 4096;
constexpr int DM_ = 1024;
constexpr int H_  = 16;
constexpr int N_  = 64;
constexpr int C_  = 64;
constexpr int E_  = 1040;
constexpr int M_  = B_ * S_;
constexpr int SHH = 72;                    // gemm smem row stride (64 + 8 pad)
constexpr int A_STAGE = 128 * SHH * 2;     // 18432 B
constexpr int B_STAGE = 256 * SHH * 2;     // 36864 B
constexpr int NSTAGE  = 3;
constexpr int GEMM_SMEM = NSTAGE * (A_STAGE + B_STAGE);   // 165888 B

constexpr int WSTR = 1028;                 // wgemm W smem stride (floats)
constexpr int XSTR = 68;                   // wgemm X smem stride (floats)
constexpr int WGEMM_SMEM = (16 * WSTR + 256 * XSTR) * 4;  // 135424 B
}

// Scratch (allocation-free: __device__ globals)
__device__ __align__(16) float  g_xw[(size_t)M_ * E_];
__device__ __align__(16) __half g_xh[(size_t)M_ * DM_];
__device__ __align__(16) __half g_yh[(size_t)M_ * DM_];
__device__ __align__(16) __half g_ipwh[(size_t)DM_ * DM_];
__device__ __align__(16) __half g_opwh[(size_t)DM_ * DM_];
__device__ __align__(16) float g_states[B_ * H_ * C_ * N_];
__device__ float g_cnorm[B_ * H_ * C_];
__device__ float g_T[B_ * H_ * C_];
__device__ __align__(16) float g_nstates[B_ * H_ * C_ * N_];
__device__ float g_nnorm[B_ * H_ * C_];

__device__ __forceinline__ uint32_t pk(float lo, float hi) {
    __half2 h = __floats2half2_rn(lo, hi);
    return *reinterpret_cast<uint32_t*>(&h);
}

__device__ __forceinline__ void mma_f16(float* c, const uint32_t* a, const uint32_t* b) {
    asm volatile(
        "mma.sync.aligned.m16n8k16.row.col.f32.f16.f16.f32 "
        "{%0,%1,%2,%3}, {%4,%5,%6,%7}, {%8,%9}, {%0,%1,%2,%3};\n"
        : "+f"(c[0]), "+f"(c[1]), "+f"(c[2]), "+f"(c[3])
        : "r"(a[0]), "r"(a[1]), "r"(a[2]), "r"(a[3]), "r"(b[0]), "r"(b[1]));
}

__device__ __forceinline__ void cp16(uint32_t smem, const void* gmem) {
    asm volatile("cp.async.cg.shared.global [%0], [%1], 16;\n" :: "r"(smem), "l"(gmem));
}

__device__ __forceinline__ void ldsm4(uint32_t* r, uint32_t addr) {
    asm volatile("ldmatrix.sync.aligned.m8n8.x4.shared.b16 {%0,%1,%2,%3}, [%4];"
                 : "=r"(r[0]), "=r"(r[1]), "=r"(r[2]), "=r"(r[3]) : "r"(addr));
}

// ---------------------------------------------------------------------------
// C0: both weight matrices fp32 -> fp16, one launch. grid 1024 x 512 thr,
// one float4 per thread.
// ---------------------------------------------------------------------------
__global__ __launch_bounds__(512)
void f2h_w_kernel(const float* __restrict__ ipw, const float* __restrict__ opw)
{
    int b = blockIdx.x;
    const float* src;
    __half* dst;
    if (b < 512) { src = ipw; dst = g_ipwh; }
    else         { src = opw; dst = g_opwh; b -= 512; }
    const int i = b * 512 + threadIdx.x;     // float4 index, 262144 per matrix
    float4 v = reinterpret_cast<const float4*>(src)[i];
    reinterpret_cast<uint2*>(dst)[i] = make_uint2(pk(v.x, v.y), pk(v.z, v.w));
}

// ---------------------------------------------------------------------------
// FP16 tensor GEMM (NT): C[M,N] = A[M,K] * B[N,K]^T, A/B fp16, C fp32.
// Block tile 128x256, 512 threads (16 warps 4m x 4n), warp tile 32x64,
// BK=64, 3-stage cp.async ring, ldmatrix.x4 with FRAGMENT DOUBLE-BUFFER.
// ---------------------------------------------------------------------------
template <bool FIRST>
__global__ __launch_bounds__(512)
void hgemm_tc(float* __restrict__ Carg, int K, int ldc)
{
    const __half* A  = FIRST ? g_xh   : g_yh;
    const __half* Bw = FIRST ? g_ipwh : g_opwh;
    float*        C  = FIRST ? g_xw   : Carg;

    extern __shared__ __align__(16) char smem[];
    const uint32_t sbase = (uint32_t)__cvta_generic_to_shared(smem);

    const int tid  = threadIdx.x;
    const int lane = tid & 31;
    const int warp = tid >> 5;
    const int wm   = warp & 3;        // m offset wm*32
    const int wn   = warp >> 2;       // n offset wn*64
    const int grp  = lane >> 2;
    const int tig  = lane & 3;

    const int m0 = blockIdx.y * 128;
    const int n0 = blockIdx.x * 256;

    const int srow = tid >> 2;            // 0..127
    const int sc16 = (tid & 3) * 16;      // half offset 0,16,32,48

    const __half* gA  = A  + (size_t)(m0 + srow) * K + sc16;
    const __half* gB0 = Bw + (size_t)(n0 + srow) * K + sc16;
    const __half* gB1 = Bw + (size_t)(n0 + 128 + srow) * K + sc16;

    const uint32_t dAoff  = (uint32_t)(srow * SHH + sc16) * 2;
    const uint32_t dB0off = dAoff;
    const uint32_t dB1off = (uint32_t)((srow + 128) * SHH + sc16) * 2;

    const uint32_t laneA = ((lane & 15) * SHH + (lane >> 4) * 8) * 2;
    const uint32_t laneB = (((lane & 7) + ((lane >> 4) << 3)) * SHH +
                            ((lane >> 3) & 1) * 8) * 2;

    float acc[2][8][4];
#pragma unroll
    for (int i = 0; i < 2; i++)
#pragma unroll
        for (int j = 0; j < 8; j++)
#pragma unroll
            for (int r = 0; r < 4; r++) acc[i][j][r] = 0.f;

    auto aBase = [&](int st) { return sbase + st * A_STAGE; };
    auto bBase = [&](int st) { return sbase + NSTAGE * A_STAGE + st * B_STAGE; };

    auto load_stage = [&](int st, int k0) {
        cp16(aBase(st) + dAoff,       gA  + k0);
        cp16(aBase(st) + dAoff + 16,  gA  + k0 + 8);
        cp16(bBase(st) + dB0off,      gB0 + k0);
        cp16(bBase(st) + dB0off + 16, gB0 + k0 + 8);
        cp16(bBase(st) + dB1off,      gB1 + k0);
        cp16(bBase(st) + dB1off + 16, gB1 + k0 + 8);
    };

    const int NIT = K >> 6;   // BK=64
    load_stage(0, 0);
    asm volatile("cp.async.commit_group;\n" ::: "memory");
    load_stage(1, 64);
    asm volatile("cp.async.commit_group;\n" ::: "memory");

    for (int it = 0; it < NIT; ++it) {
        const int cur = it % NSTAGE;
        if (it < NIT - 1) {
            asm volatile("cp.async.wait_group 1;\n" ::: "memory");
        } else {
            asm volatile("cp.async.wait_group 0;\n" ::: "memory");
        }
        __syncthreads();

        if (it + 2 < NIT) {
            load_stage((it + 2) % NSTAGE, (it + 2) << 6);
            asm volatile("cp.async.commit_group;\n" ::: "memory");
        }

        const uint32_t aSt = aBase(cur);
        const uint32_t bSt = bBase(cur);

        // fragment double-buffer over the 4 ks steps
        uint32_t afr[2][2][4], bfr[2][4][4];
        auto ldfrag = [&](int buf, int ks) {
#pragma unroll
            for (int mt = 0; mt < 2; mt++)
                ldsm4(afr[buf][mt],
                      aSt + (wm * 32 + mt * 16) * (SHH * 2) + ks * 32 + laneA);
#pragma unroll
            for (int np = 0; np < 4; np++)
                ldsm4(bfr[buf][np],
                      bSt + (wn * 64 + np * 16) * (SHH * 2) + ks * 32 + laneB);
        };
        ldfrag(0, 0);
#pragma unroll
        for (int ks = 0; ks < 4; ks++) {
            const int cb = ks & 1;
            if (ks < 3) ldfrag(cb ^ 1, ks + 1);
#pragma unroll
            for (int mt = 0; mt < 2; mt++)
#pragma unroll
                for (int nt = 0; nt < 8; nt++)
                    mma_f16(acc[mt][nt], afr[cb][mt], &bfr[cb][nt >> 1][(nt & 1) * 2]);
        }
    }
    __syncthreads();

#pragma unroll
    for (int mt = 0; mt < 2; mt++) {
        const int row = m0 + wm * 32 + mt * 16 + grp;
#pragma unroll
        for (int nt = 0; nt < 8; nt++) {
            const int col = n0 + wn * 64 + nt * 8 + tig * 2;
            *reinterpret_cast<float2*>(&C[(size_t)row * ldc + col]) =
                make_float2(acc[mt][nt][0], acc[mt][nt][1]);
            *reinterpret_cast<float2*>(&C[(size_t)(row + 8) * ldc + col]) =
                make_float2(acc[mt][nt][2], acc[mt][nt][3]);
        }
    }
}

// ---------------------------------------------------------------------------
// K1b: skinny fp32 GEMM for the 16 "w" columns + fused x fp32->fp16 emit.
// 512 threads, 256 rows/block, W fully resident in smem, float4 LDS paths.
// grid = M/256 = 128 blocks (single wave).
// ---------------------------------------------------------------------------
__global__ __launch_bounds__(512)
void wgemm_kernel(const float* __restrict__ x, const float* __restrict__ ipw)
{
    extern __shared__ __align__(16) float fsm[];
    float* Ws = fsm;                 // [16][WSTR]
    float* Xs = fsm + 16 * WSTR;     // [256][XSTR]

    const int tid = threadIdx.x;
    const int cq4 = (tid & 3) * 4;   // col group: cols cq4..cq4+3
    const int rg  = tid >> 2;        // 0..127 -> rows rg, rg+128
    const int m0  = blockIdx.x * 256;

    // Load all of W (rows 1024..1039 of ipw) once: 4096 float4s.
    const float4* wsrc = reinterpret_cast<const float4*>(ipw + (size_t)1024 * DM_);
#pragma unroll
    for (int j = 0; j < 8; j++) {
        const int w4 = j * 512 + tid;        // 0..4095
        float4 v = wsrc[w4];
        const int r  = w4 >> 8;              // 0..15
        const int cw = (w4 & 255) * 4;       // 0..1020
        *reinterpret_cast<float4*>(Ws + r * WSTR + cw) = v;
    }

    float acc[2][4];
#pragma unroll
    for (int r = 0; r < 2; r++)
#pragma unroll
        for (int c = 0; c < 4; c++) acc[r][c] = 0.f;

    const int lrow = tid >> 1;           // 0..255
    const int lk0  = (tid & 1) * 32;

    for (int kc = 0; kc < 16; kc++) {
        const int k0 = kc * 64;
        // stage X tile (256 x 64) + fused fp16 emit
        {
            const float* xsrc = x + (size_t)(m0 + lrow) * DM_ + k0 + lk0;
            __half* xhd = g_xh + (size_t)(m0 + lrow) * DM_ + k0 + lk0;
            float* xdst = Xs + lrow * XSTR + lk0;
#pragma unroll
            for (int q = 0; q < 8; q++) {
                float4 v = *reinterpret_cast<const float4*>(xsrc + q * 4);
                *reinterpret_cast<float4*>(xdst + q * 4) = v;
                *reinterpret_cast<uint2*>(xhd + q * 4) =
                    make_uint2(pk(v.x, v.y), pk(v.z, v.w));
            }
        }
        __syncthreads();

#pragma unroll 4
        for (int k4 = 0; k4 < 16; k4++) {
            float4 xv0 = *reinterpret_cast<const float4*>(Xs + rg * XSTR + k4 * 4);
            float4 xv1 = *reinterpret_cast<const float4*>(Xs + (rg + 128) * XSTR + k4 * 4);
#pragma unroll
            for (int cc = 0; cc < 4; cc++) {
                float4 wv = *reinterpret_cast<const float4*>(
                    Ws + (cq4 + cc) * WSTR + k0 + k4 * 4);
                acc[0][cc] = fmaf(xv0.x, wv.x, acc[0][cc]);
                acc[0][cc] = fmaf(xv0.y, wv.y, acc[0][cc]);
                acc[0][cc] = fmaf(xv0.z, wv.z, acc[0][cc]);
                acc[0][cc] = fmaf(xv0.w, wv.w, acc[0][cc]);
                acc[1][cc] = fmaf(xv1.x, wv.x, acc[1][cc]);
                acc[1][cc] = fmaf(xv1.y, wv.y, acc[1][cc]);
                acc[1][cc] = fmaf(xv1.z, wv.z, acc[1][cc]);
                acc[1][cc] = fmaf(xv1.w, wv.w, acc[1][cc]);
            }
        }
        __syncthreads();
    }

#pragma unroll
    for (int r = 0; r < 2; r++) {
        const int row = m0 + rg + r * 128;
        *reinterpret_cast<float4*>(&g_xw[(size_t)row * E_ + 1024 + cq4]) =
            make_float4(acc[r][0], acc[r][1], acc[r][2], acc[r][3]);
    }
}

// ---------------------------------------------------------------------------
// K2: per-(b,h,c) chunk stats — 4 chunks per block (64,4).
// ---------------------------------------------------------------------------
__global__ __launch_bounds__(256)
void chunk_stats_kernel(const float* __restrict__ conv_w,
                        const float* __restrict__ conv_b,
                        const float* __restrict__ w_base)
{
    const int ty = threadIdx.y;
    const int c  = blockIdx.x * 4 + ty;
    const int h  = blockIdx.y, b = blockIdx.z;
    const int n  = threadIdx.x;

    __shared__ float sS[4][64];
    __shared__ float sE[4][64];
    __shared__ float sMin[4];

    const int ch = h * 64 + n;
    const float cw0 = conv_w[ch * 4 + 0];
    const float cw1 = conv_w[ch * 4 + 1];
    const float cw2 = conv_w[ch * 4 + 2];
    const float cw3 = conv_w[ch * 4 + 3];
    const float cb  = conv_b[ch];

    const int s0 = c * 64;
    const float* xwb = g_xw + (size_t)b * S_ * E_;
    const float* xp  = xwb + (size_t)s0 * E_ + h * 64 + n;

    float xm3 = 0.f, xm2 = 0.f, xm1 = 0.f;
    if (c > 0) {
        xm3 = xp[-(ptrdiff_t)(3 * E_)];
        xm2 = xp[-(ptrdiff_t)(2 * E_)];
        xm1 = xp[-(ptrdiff_t)(1 * E_)];
    }

    sS[ty][n] = xwb[(size_t)(s0 + n) * E_ + 1024 + h] * w_base[h];
    __syncthreads();

    if (n == 0) {
        float run = 0.f, mn = 3.4e38f;
        for (int i = 0; i < 64; i++) {
            run += sS[ty][i];
            sS[ty][i] = run;
            mn = fminf(mn, run);
        }
        sMin[ty] = mn;
    }
    __syncthreads();
    sE[ty][n] = __expf(-sS[ty][n]);
    __syncthreads();

    float r = 0.f, rn = 0.f;
#pragma unroll 4
    for (int i = 0; i < 64; i++) {
        const float x0 = xp[(size_t)i * E_];
        const float xv = cb + cw0 * xm3 + cw1 * xm2 + cw2 * xm1 + cw3 * x0;
        xm3 = xm2; xm2 = xm1; xm1 = x0;
        const float e = sE[ty][i];
        r  = fmaf(e, xv, r);
        rn += e;
    }

    const float sc  = __expf(sMin[ty]);
    const int   idx = (b * H_ + h) * C_ + c;
    g_states[idx * N_ + n] = sc * r;
    if (n == 0) {
        g_cnorm[idx] = sc * rn;
        g_T[idx]     = sS[ty][63];
    }
}

// ---------------------------------------------------------------------------
// K3: per-(b,h) cross-chunk scan — 256 threads.
// ---------------------------------------------------------------------------
__global__ __launch_bounds__(256)
void chunk_scan_kernel()
{
    const int h = blockIdx.x, b = blockIdx.y;
    const int tid = threadIdx.x;
    const int n  = tid & 63;
    const int zq = tid >> 6;

    __shared__ float G[65];
    __shared__ float MP[64];
    __shared__ float W[64][64];
    __shared__ float st[64][64];
    __shared__ float cn[64];

    const int base = (b * H_ + h) * C_;

    for (int idx = tid; idx < 4096; idx += 256)
        st[idx >> 6][idx & 63] = g_states[(size_t)base * N_ + idx];
    if (tid < 64) cn[tid] = g_cnorm[base + tid];
    __syncthreads();

    if (tid == 0) {
        float run = 0.f;
        G[0] = 0.f;
        for (int c = 0; c < 64; c++) { run += g_T[base + c]; G[c + 1] = run; }
        float mn = 3.4e38f;
        for (int z = 0; z < 64; z++) { mn = fminf(mn, G[z]); MP[z] = mn; }
    }
    __syncthreads();

    for (int idx = tid; idx < 4096; idx += 256) {
        const int z = idx >> 6, cp = idx & 63;
        W[z][cp] = (cp < z) ? __expf(MP[z] - G[cp + 1]) : 0.f;
    }
    __syncthreads();

    for (int z = zq; z < 64; z += 4) {
        float accv = 0.f;
        for (int cp = 0; cp < z; cp++) accv = fmaf(W[z][cp], st[cp][n], accv);
        g_nstates[(base + z) * N_ + n] = accv;
    }
    if (tid < 64) {
        float accn = 0.f;
        for (int cp = 0; cp < tid; cp++) accn = fmaf(W[tid][cp], cn[cp], accn);
        g_nnorm[base + tid] = accn;
    }
}

// ---------------------------------------------------------------------------
// K4: per-(b,h,c) combine -> y fp16 — 4 chunks per block (64,4).
// ---------------------------------------------------------------------------
__global__ __launch_bounds__(256)
void combine_kernel(const float* __restrict__ conv_w,
                    const float* __restrict__ conv_b,
                    const float* __restrict__ w_base)
{
    const int ty = threadIdx.y;
    const int c  = blockIdx.x * 4 + ty;
    const int h  = blockIdx.y, b = blockIdx.z;
    const int n  = threadIdx.x;

    __shared__ float sS[4][64];
    __shared__ float sE[4][64], sEMP[4][64], sSDO[4][64];
    __shared__ float sMP[4][64];
    __shared__ float sMax[4];

    const int ch = h * 64 + n;
    const float cw0 = conv_w[ch * 4 + 0];
    const float cw1 = conv_w[ch * 4 + 1];
    const float cw2 = conv_w[ch * 4 + 2];
    const float cw3 = conv_w[ch * 4 + 3];
    const float cb  = conv_b[ch];

    const int s0 = c * 64;
    const float* xwb = g_xw + (size_t)b * S_ * E_;
    const float* xp  = xwb + (size_t)s0 * E_ + h * 64 + n;

    float xm3 = 0.f, xm2 = 0.f, xm1 = 0.f;
    if (c > 0) {
        xm3 = xp[-(ptrdiff_t)(3 * E_)];
        xm2 = xp[-(ptrdiff_t)(2 * E_)];
        xm1 = xp[-(ptrdiff_t)(1 * E_)];
    }

    sS[ty][n] = xwb[(size_t)(s0 + n) * E_ + 1024 + h] * w_base[h];
    __syncthreads();

    if (n == 0) {
        float run = 0.f, mn = 3.4e38f, mx = -3.4e38f;
        for (int i = 0; i < 64; i++) {
            run += sS[ty][i];
            sS[ty][i] = run;
            mn = fminf(mn, run);
            sMP[ty][i] = mn;
            mx = fmaxf(mx, run);
        }
        sMax[ty] = mx;
    }
    __syncthreads();
    sE[ty][n]   = __expf(-sS[ty][n]);
    sEMP[ty][n] = __expf(sMP[ty][n]);
    sSDO[ty][n] = __expf(sS[ty][n] - sMax[ty]);
    __syncthreads();

    const int idx = (b * H_ + h) * C_ + c;
    const float ns = g_nstates[idx * N_ + n];
    const float nn = g_nnorm[idx];

    float r = 0.f, rn = 0.f;
    __half* yout = g_yh + (size_t)(b * S_ + s0) * DM_ + h * 64 + n;

#pragma unroll 4
    for (int i = 0; i < 64; i++) {
        const float x0 = xp[(size_t)i * E_];
        const float xv = cb + cw0 * xm3 + cw1 * xm2 + cw2 * xm1 + cw3 * x0;
        xm3 = xm2; xm2 = xm1; xm1 = x0;
        const float e = sE[ty][i];
        r  = fmaf(e, xv, r);
        rn += e;
        const float emp = sEMP[ty][i];
        const float sdo = sSDO[ty][i];
        const float num = fmaf(sdo, ns, emp * r);
        const float den = fmaf(sdo, nn, emp * rn);
        yout[(size_t)i * DM_] = __float2half_rn(num / den);
    }
}

// ---------------------------------------------------------------------------
// Launch
// ---------------------------------------------------------------------------
extern "C" void kernel_launch(void* const* d_in, const int* in_sizes, int n_in,
                              void* d_out, int out_size)
{
    const float *x = nullptr, *ipw = nullptr, *cw = nullptr,
                *cb = nullptr, *wb = nullptr, *opw = nullptr;
    for (int i = 0; i < n_in; i++) {
        switch (in_sizes[i]) {
            case M_ * DM_:  x   = (const float*)d_in[i]; break;
            case E_ * DM_:  ipw = (const float*)d_in[i]; break;
            case DM_ * 4:   cw  = (const float*)d_in[i]; break;
            case DM_:       cb  = (const float*)d_in[i]; break;
            case H_:        wb  = (const float*)d_in[i]; break;
            case DM_ * DM_: opw = (const float*)d_in[i]; break;
        }
    }

    static bool attr_done = false;
    if (!attr_done) {
        cudaFuncSetAttribute(hgemm_tc<true>,
                             cudaFuncAttributeMaxDynamicSharedMemorySize, GEMM_SMEM);
        cudaFuncSetAttribute(hgemm_tc<false>,
                             cudaFuncAttributeMaxDynamicSharedMemorySize, GEMM_SMEM);
        cudaFuncSetAttribute(wgemm_kernel,
                             cudaFuncAttributeMaxDynamicSharedMemorySize, WGEMM_SMEM);
        attr_done = true;
    }

    // C0: weight fp32 -> fp16 (both matrices, one launch)
    f2h_w_kernel<<<1024, 512>>>(ipw, opw);

    // K1b: w-cols fp32 GEMM + x fp16 emit (single wave)
    wgemm_kernel<<<M_ / 256, 512, WGEMM_SMEM>>>(x, ipw);

    // K1a: xi = x @ in_proj_w[:1024]^T (fp16 TC)
    hgemm_tc<true><<<dim3(DM_ / 256, M_ / 128), 512, GEMM_SMEM>>>(nullptr, DM_, E_);

    // K2: per-chunk stats
    chunk_stats_kernel<<<dim3(C_ / 4, H_, B_), dim3(64, 4)>>>(cw, cb, wb);

    // K3: cross-chunk scan
    chunk_scan_kernel<<<dim3(H_, B_), 256>>>();

    // K4: combine -> y (fp16)
    combine_kernel<<<dim3(C_ / 4, H_, B_), dim3(64, 4)>>>(cw, cb, wb);

    // K5: out = y @ out_proj_w^T (fp16 TC)
    hgemm_tc<false><<<dim3(DM_ / 256, M_ / 128), 512, GEMM_SMEM>>>(
        (float*)d_out, DM_, DM_);
}

// round 11
// speedup vs baseline: 1.8690x; 1.0365x over previous
#include <cuda_runtime.h>
#include <cuda_fp16.h>
#include <cstdint>
#include <cstddef>

// ---------------------------------------------------------------------------
// DecayBlock (Mamba-2 SSD block) — round 11: shrink the intermediates.
//   * xi activations stored fp16 (g_xih) directly from hgemm<true> epilogue
//   * w columns in dense fp32 g_wc[M][16] (exponentiated -> stays exact)
//   * stats/combine stream fp16 (half the DRAM traffic, coalesced rows)
// ---------------------------------------------------------------------------

namespace {
constexpr int B_  = 8;
constexpr int S_  = 4096;
constexpr int DM_ = 1024;
constexpr int H_  = 16;
constexpr int N_  = 64;
constexpr int C_  = 64;
constexpr int M_  = B_ * S_;
constexpr int SHH = 72;                    // gemm smem row stride (64 + 8 pad)
constexpr int A_STAGE = 128 * SHH * 2;     // 18432 B
constexpr int B_STAGE = 256 * SHH * 2;     // 36864 B
constexpr int NSTAGE  = 3;
constexpr int GEMM_SMEM = NSTAGE * (A_STAGE + B_STAGE);   // 165888 B

constexpr int WSTR = 1028;                 // wgemm W smem stride (floats)
constexpr int XSTR = 68;                   // wgemm X smem stride (floats)
constexpr int WGEMM_SMEM = (16 * WSTR + 256 * XSTR) * 4;  // 135424 B
}

// Scratch (allocation-free: __device__ globals)
__device__ __align__(16) __half g_xih[(size_t)M_ * DM_];   // conv input (fp16)
__device__ __align__(16) float  g_wc[(size_t)M_ * H_];     // w columns (fp32)
__device__ __align__(16) __half g_xh[(size_t)M_ * DM_];    // x fp16
__device__ __align__(16) __half g_yh[(size_t)M_ * DM_];    // y fp16
__device__ __align__(16) __half g_ipwh[(size_t)DM_ * DM_];
__device__ __align__(16) __half g_opwh[(size_t)DM_ * DM_];
__device__ __align__(16) float g_states[B_ * H_ * C_ * N_];
__device__ float g_cnorm[B_ * H_ * C_];
__device__ float g_T[B_ * H_ * C_];
__device__ __align__(16) float g_nstates[B_ * H_ * C_ * N_];
__device__ float g_nnorm[B_ * H_ * C_];

__device__ __forceinline__ uint32_t pk(float lo, float hi) {
    __half2 h = __floats2half2_rn(lo, hi);
    return *reinterpret_cast<uint32_t*>(&h);
}

__device__ __forceinline__ void mma_f16(float* c, const uint32_t* a, const uint32_t* b) {
    asm volatile(
        "mma.sync.aligned.m16n8k16.row.col.f32.f16.f16.f32 "
        "{%0,%1,%2,%3}, {%4,%5,%6,%7}, {%8,%9}, {%0,%1,%2,%3};\n"
        : "+f"(c[0]), "+f"(c[1]), "+f"(c[2]), "+f"(c[3])
        : "r"(a[0]), "r"(a[1]), "r"(a[2]), "r"(a[3]), "r"(b[0]), "r"(b[1]));
}

__device__ __forceinline__ void cp16(uint32_t smem, const void* gmem) {
    asm volatile("cp.async.cg.shared.global [%0], [%1], 16;\n" :: "r"(smem), "l"(gmem));
}

__device__ __forceinline__ void ldsm4(uint32_t* r, uint32_t addr) {
    asm volatile("ldmatrix.sync.aligned.m8n8.x4.shared.b16 {%0,%1,%2,%3}, [%4];"
                 : "=r"(r[0]), "=r"(r[1]), "=r"(r[2]), "=r"(r[3]) : "r"(addr));
}

// ---------------------------------------------------------------------------
// C0: both weight matrices fp32 -> fp16, one launch.
// ---------------------------------------------------------------------------
__global__ __launch_bounds__(512)
void f2h_w_kernel(const float* __restrict__ ipw, const float* __restrict__ opw)
{
    int b = blockIdx.x;
    const float* src;
    __half* dst;
    if (b < 512) { src = ipw; dst = g_ipwh; }
    else         { src = opw; dst = g_opwh; b -= 512; }
    const int i = b * 512 + threadIdx.x;
    float4 v = reinterpret_cast<const float4*>(src)[i];
    reinterpret_cast<uint2*>(dst)[i] = make_uint2(pk(v.x, v.y), pk(v.z, v.w));
}

// ---------------------------------------------------------------------------
// FP16 tensor GEMM (NT): 128x256 block, 512 thr (16 warps 4m x 4n),
// warp tile 32x64, BK=64, 3-stage cp.async, ldmatrix double-buffer.
// FIRST: A=g_xh, B=g_ipwh, C=g_xih (fp16 out). else: A=g_yh, B=g_opwh,
// C=Carg fp32.
// ---------------------------------------------------------------------------
template <bool FIRST>
__global__ __launch_bounds__(512)
void hgemm_tc(float* __restrict__ Carg, int K)
{
    const __half* A  = FIRST ? g_xh   : g_yh;
    const __half* Bw = FIRST ? g_ipwh : g_opwh;

    extern __shared__ __align__(16) char smem[];
    const uint32_t sbase = (uint32_t)__cvta_generic_to_shared(smem);

    const int tid  = threadIdx.x;
    const int lane = tid & 31;
    const int warp = tid >> 5;
    const int wm   = warp & 3;
    const int wn   = warp >> 2;
    const int grp  = lane >> 2;
    const int tig  = lane & 3;

    const int m0 = blockIdx.y * 128;
    const int n0 = blockIdx.x * 256;

    const int srow = tid >> 2;
    const int sc16 = (tid & 3) * 16;

    const __half* gA  = A  + (size_t)(m0 + srow) * K + sc16;
    const __half* gB0 = Bw + (size_t)(n0 + srow) * K + sc16;
    const __half* gB1 = Bw + (size_t)(n0 + 128 + srow) * K + sc16;

    const uint32_t dAoff  = (uint32_t)(srow * SHH + sc16) * 2;
    const uint32_t dB0off = dAoff;
    const uint32_t dB1off = (uint32_t)((srow + 128) * SHH + sc16) * 2;

    const uint32_t laneA = ((lane & 15) * SHH + (lane >> 4) * 8) * 2;
    const uint32_t laneB = (((lane & 7) + ((lane >> 4) << 3)) * SHH +
                            ((lane >> 3) & 1) * 8) * 2;

    float acc[2][8][4];
#pragma unroll
    for (int i = 0; i < 2; i++)
#pragma unroll
        for (int j = 0; j < 8; j++)
#pragma unroll
            for (int r = 0; r < 4; r++) acc[i][j][r] = 0.f;

    auto aBase = [&](int st) { return sbase + st * A_STAGE; };
    auto bBase = [&](int st) { return sbase + NSTAGE * A_STAGE + st * B_STAGE; };

    auto load_stage = [&](int st, int k0) {
        cp16(aBase(st) + dAoff,       gA  + k0);
        cp16(aBase(st) + dAoff + 16,  gA  + k0 + 8);
        cp16(bBase(st) + dB0off,      gB0 + k0);
        cp16(bBase(st) + dB0off + 16, gB0 + k0 + 8);
        cp16(bBase(st) + dB1off,      gB1 + k0);
        cp16(bBase(st) + dB1off + 16, gB1 + k0 + 8);
    };

    const int NIT = K >> 6;
    load_stage(0, 0);
    asm volatile("cp.async.commit_group;\n" ::: "memory");
    load_stage(1, 64);
    asm volatile("cp.async.commit_group;\n" ::: "memory");

    for (int it = 0; it < NIT; ++it) {
        const int cur = it % NSTAGE;
        if (it < NIT - 1) {
            asm volatile("cp.async.wait_group 1;\n" ::: "memory");
        } else {
            asm volatile("cp.async.wait_group 0;\n" ::: "memory");
        }
        __syncthreads();

        if (it + 2 < NIT) {
            load_stage((it + 2) % NSTAGE, (it + 2) << 6);
            asm volatile("cp.async.commit_group;\n" ::: "memory");
        }

        const uint32_t aSt = aBase(cur);
        const uint32_t bSt = bBase(cur);

        uint32_t afr[2][2][4], bfr[2][4][4];
        auto ldfrag = [&](int buf, int ks) {
#pragma unroll
            for (int mt = 0; mt < 2; mt++)
                ldsm4(afr[buf][mt],
                      aSt + (wm * 32 + mt * 16) * (SHH * 2) + ks * 32 + laneA);
#pragma unroll
            for (int np = 0; np < 4; np++)
                ldsm4(bfr[buf][np],
                      bSt + (wn * 64 + np * 16) * (SHH * 2) + ks * 32 + laneB);
        };
        ldfrag(0, 0);
#pragma unroll
        for (int ks = 0; ks < 4; ks++) {
            const int cb = ks & 1;
            if (ks < 3) ldfrag(cb ^ 1, ks + 1);
#pragma unroll
            for (int mt = 0; mt < 2; mt++)
#pragma unroll
                for (int nt = 0; nt < 8; nt++)
                    mma_f16(acc[mt][nt], afr[cb][mt], &bfr[cb][nt >> 1][(nt & 1) * 2]);
        }
    }
    __syncthreads();

#pragma unroll
    for (int mt = 0; mt < 2; mt++) {
        const int row = m0 + wm * 32 + mt * 16 + grp;
#pragma unroll
        for (int nt = 0; nt < 8; nt++) {
            const int col = n0 + wn * 64 + nt * 8 + tig * 2;
            if (FIRST) {
                // fp16 output (xi feeds conv; fp16 precision already accepted)
                *reinterpret_cast<uint32_t*>(
                    &g_xih[(size_t)row * DM_ + col]) = pk(acc[mt][nt][0], acc[mt][nt][1]);
                *reinterpret_cast<uint32_t*>(
                    &g_xih[(size_t)(row + 8) * DM_ + col]) = pk(acc[mt][nt][2], acc[mt][nt][3]);
            } else {
                *reinterpret_cast<float2*>(&Carg[(size_t)row * DM_ + col]) =
                    make_float2(acc[mt][nt][0], acc[mt][nt][1]);
                *reinterpret_cast<float2*>(&Carg[(size_t)(row + 8) * DM_ + col]) =
                    make_float2(acc[mt][nt][2], acc[mt][nt][3]);
            }
        }
    }
}

// ---------------------------------------------------------------------------
// K1b: w-cols fp32 GEMM (dense g_wc out) + fused x fp32->fp16 emit.
// ---------------------------------------------------------------------------
__global__ __launch_bounds__(512)
void wgemm_kernel(const float* __restrict__ x, const float* __restrict__ ipw)
{
    extern __shared__ __align__(16) float fsm[];
    float* Ws = fsm;                 // [16][WSTR]
    float* Xs = fsm + 16 * WSTR;     // [256][XSTR]

    const int tid = threadIdx.x;
    const int cq4 = (tid & 3) * 4;
    const int rg  = tid >> 2;
    const int m0  = blockIdx.x * 256;

    const float4* wsrc = reinterpret_cast<const float4*>(ipw + (size_t)1024 * DM_);
#pragma unroll
    for (int j = 0; j < 8; j++) {
        const int w4 = j * 512 + tid;
        float4 v = wsrc[w4];
        const int r  = w4 >> 8;
        const int cw = (w4 & 255) * 4;
        *reinterpret_cast<float4*>(Ws + r * WSTR + cw) = v;
    }

    float acc[2][4];
#pragma unroll
    for (int r = 0; r < 2; r++)
#pragma unroll
        for (int c = 0; c < 4; c++) acc[r][c] = 0.f;

    const int lrow = tid >> 1;
    const int lk0  = (tid & 1) * 32;

    for (int kc = 0; kc < 16; kc++) {
        const int k0 = kc * 64;
        {
            const float* xsrc = x + (size_t)(m0 + lrow) * DM_ + k0 + lk0;
            __half* xhd = g_xh + (size_t)(m0 + lrow) * DM_ + k0 + lk0;
            float* xdst = Xs + lrow * XSTR + lk0;
#pragma unroll
            for (int q = 0; q < 8; q++) {
                float4 v = *reinterpret_cast<const float4*>(xsrc + q * 4);
                *reinterpret_cast<float4*>(xdst + q * 4) = v;
                *reinterpret_cast<uint2*>(xhd + q * 4) =
                    make_uint2(pk(v.x, v.y), pk(v.z, v.w));
            }
        }
        __syncthreads();

#pragma unroll 4
        for (int k4 = 0; k4 < 16; k4++) {
            float4 xv0 = *reinterpret_cast<const float4*>(Xs + rg * XSTR + k4 * 4);
            float4 xv1 = *reinterpret_cast<const float4*>(Xs + (rg + 128) * XSTR + k4 * 4);
#pragma unroll
            for (int cc = 0; cc < 4; cc++) {
                float4 wv = *reinterpret_cast<const float4*>(
                    Ws + (cq4 + cc) * WSTR + k0 + k4 * 4);
                acc[0][cc] = fmaf(xv0.x, wv.x, acc[0][cc]);
                acc[0][cc] = fmaf(xv0.y, wv.y, acc[0][cc]);
                acc[0][cc] = fmaf(xv0.z, wv.z, acc[0][cc]);
                acc[0][cc] = fmaf(xv0.w, wv.w, acc[0][cc]);
                acc[1][cc] = fmaf(xv1.x, wv.x, acc[1][cc]);
                acc[1][cc] = fmaf(xv1.y, wv.y, acc[1][cc]);
                acc[1][cc] = fmaf(xv1.z, wv.z, acc[1][cc]);
                acc[1][cc] = fmaf(xv1.w, wv.w, acc[1][cc]);
            }
        }
        __syncthreads();
    }

#pragma unroll
    for (int r = 0; r < 2; r++) {
        const int row = m0 + rg + r * 128;
        *reinterpret_cast<float4*>(&g_wc[(size_t)row * H_ + cq4]) =
            make_float4(acc[r][0], acc[r][1], acc[r][2], acc[r][3]);
    }
}

// ---------------------------------------------------------------------------
// K2: per-(b,h,c) chunk stats — fp16 xi stream, rolling conv window.
// ---------------------------------------------------------------------------
__global__ __launch_bounds__(256)
void chunk_stats_kernel(const float* __restrict__ conv_w,
                        const float* __restrict__ conv_b,
                        const float* __restrict__ w_base)
{
    const int ty = threadIdx.y;
    const int c  = blockIdx.x * 4 + ty;
    const int h  = blockIdx.y, b = blockIdx.z;
    const int n  = threadIdx.x;

    __shared__ float sS[4][64];
    __shared__ float sE[4][64];
    __shared__ float sMin[4];

    const int ch = h * 64 + n;
    const float cw0 = conv_w[ch * 4 + 0];
    const float cw1 = conv_w[ch * 4 + 1];
    const float cw2 = conv_w[ch * 4 + 2];
    const float cw3 = conv_w[ch * 4 + 3];
    const float cb  = conv_b[ch];

    const int s0 = c * 64;
    const __half* xp = g_xih + (size_t)(b * S_ + s0) * DM_ + h * 64 + n;

    float xm3 = 0.f, xm2 = 0.f, xm1 = 0.f;
    if (c > 0) {
        xm3 = __half2float(xp[-(ptrdiff_t)(3 * DM_)]);
        xm2 = __half2float(xp[-(ptrdiff_t)(2 * DM_)]);
        xm1 = __half2float(xp[-(ptrdiff_t)(1 * DM_)]);
    }

    sS[ty][n] = g_wc[(size_t)(b * S_ + s0 + n) * H_ + h] * w_base[h];
    __syncthreads();

    if (n == 0) {
        float run = 0.f, mn = 3.4e38f;
        for (int i = 0; i < 64; i++) {
            run += sS[ty][i];
            sS[ty][i] = run;
            mn = fminf(mn, run);
        }
        sMin[ty] = mn;
    }
    __syncthreads();
    sE[ty][n] = __expf(-sS[ty][n]);
    __syncthreads();

    float r = 0.f, rn = 0.f;
#pragma unroll 4
    for (int i = 0; i < 64; i++) {
        const float x0 = __half2float(xp[(size_t)i * DM_]);
        const float xv = cb + cw0 * xm3 + cw1 * xm2 + cw2 * xm1 + cw3 * x0;
        xm3 = xm2; xm2 = xm1; xm1 = x0;
        const float e = sE[ty][i];
        r  = fmaf(e, xv, r);
        rn += e;
    }

    const float sc  = __expf(sMin[ty]);
    const int   idx = (b * H_ + h) * C_ + c;
    g_states[idx * N_ + n] = sc * r;
    if (n == 0) {
        g_cnorm[idx] = sc * rn;
        g_T[idx]     = sS[ty][63];
    }
}

// ---------------------------------------------------------------------------
// K3: per-(b,h) cross-chunk scan — 256 threads.
// ---------------------------------------------------------------------------
__global__ __launch_bounds__(256)
void chunk_scan_kernel()
{
    const int h = blockIdx.x, b = blockIdx.y;
    const int tid = threadIdx.x;
    const int n  = tid & 63;
    const int zq = tid >> 6;

    __shared__ float G[65];
    __shared__ float MP[64];
    __shared__ float W[64][64];
    __shared__ float st[64][64];
    __shared__ float cn[64];

    const int base = (b * H_ + h) * C_;

    for (int idx = tid; idx < 4096; idx += 256)
        st[idx >> 6][idx & 63] = g_states[(size_t)base * N_ + idx];
    if (tid < 64) cn[tid] = g_cnorm[base + tid];
    __syncthreads();

    if (tid == 0) {
        float run = 0.f;
        G[0] = 0.f;
        for (int c = 0; c < 64; c++) { run += g_T[base + c]; G[c + 1] = run; }
        float mn = 3.4e38f;
        for (int z = 0; z < 64; z++) { mn = fminf(mn, G[z]); MP[z] = mn; }
    }
    __syncthreads();

    for (int idx = tid; idx < 4096; idx += 256) {
        const int z = idx >> 6, cp = idx & 63;
        W[z][cp] = (cp < z) ? __expf(MP[z] - G[cp + 1]) : 0.f;
    }
    __syncthreads();

    for (int z = zq; z < 64; z += 4) {
        float accv = 0.f;
        for (int cp = 0; cp < z; cp++) accv = fmaf(W[z][cp], st[cp][n], accv);
        g_nstates[(base + z) * N_ + n] = accv;
    }
    if (tid < 64) {
        float accn = 0.f;
        for (int cp = 0; cp < tid; cp++) accn = fmaf(W[tid][cp], cn[cp], accn);
        g_nnorm[base + tid] = accn;
    }
}

// ---------------------------------------------------------------------------
// K4: per-(b,h,c) combine -> y fp16 — fp16 xi stream.
// ---------------------------------------------------------------------------
__global__ __launch_bounds__(256)
void combine_kernel(const float* __restrict__ conv_w,
                    const float* __restrict__ conv_b,
                    const float* __restrict__ w_base)
{
    const int ty = threadIdx.y;
    const int c  = blockIdx.x * 4 + ty;
    const int h  = blockIdx.y, b = blockIdx.z;
    const int n  = threadIdx.x;

    __shared__ float sS[4][64];
    __shared__ float sE[4][64], sEMP[4][64], sSDO[4][64];
    __shared__ float sMP[4][64];
    __shared__ float sMax[4];

    const int ch = h * 64 + n;
    const float cw0 = conv_w[ch * 4 + 0];
    const float cw1 = conv_w[ch * 4 + 1];
    const float cw2 = conv_w[ch * 4 + 2];
    const float cw3 = conv_w[ch * 4 + 3];
    const float cb  = conv_b[ch];

    const int s0 = c * 64;
    const __half* xp = g_xih + (size_t)(b * S_ + s0) * DM_ + h * 64 + n;

    float xm3 = 0.f, xm2 = 0.f, xm1 = 0.f;
    if (c > 0) {
        xm3 = __half2float(xp[-(ptrdiff_t)(3 * DM_)]);
        xm2 = __half2float(xp[-(ptrdiff_t)(2 * DM_)]);
        xm1 = __half2float(xp[-(ptrdiff_t)(1 * DM_)]);
    }

    sS[ty][n] = g_wc[(size_t)(b * S_ + s0 + n) * H_ + h] * w_base[h];
    __syncthreads();

    if (n == 0) {
        float run = 0.f, mn = 3.4e38f, mx = -3.4e38f;
        for (int i = 0; i < 64; i++) {
            run += sS[ty][i];
            sS[ty][i] = run;
            mn = fminf(mn, run);
            sMP[ty][i] = mn;
            mx = fmaxf(mx, run);
        }
        sMax[ty] = mx;
    }
    __syncthreads();
    sE[ty][n]   = __expf(-sS[ty][n]);
    sEMP[ty][n] = __expf(sMP[ty][n]);
    sSDO[ty][n] = __expf(sS[ty][n] - sMax[ty]);
    __syncthreads();

    const int idx = (b * H_ + h) * C_ + c;
    const float ns = g_nstates[idx * N_ + n];
    const float nn = g_nnorm[idx];

    float r = 0.f, rn = 0.f;
    __half* yout = g_yh + (size_t)(b * S_ + s0) * DM_ + h * 64 + n;

#pragma unroll 4
    for (int i = 0; i < 64; i++) {
        const float x0 = __half2float(xp[(size_t)i * DM_]);
        const float xv = cb + cw0 * xm3 + cw1 * xm2 + cw2 * xm1 + cw3 * x0;
        xm3 = xm2; xm2 = xm1; xm1 = x0;
        const float e = sE[ty][i];
        r  = fmaf(e, xv, r);
        rn += e;
        const float emp = sEMP[ty][i];
        const float sdo = sSDO[ty][i];
        const float num = fmaf(sdo, ns, emp * r);
        const float den = fmaf(sdo, nn, emp * rn);
        yout[(size_t)i * DM_] = __float2half_rn(num / den);
    }
}

// ---------------------------------------------------------------------------
// Launch
// ---------------------------------------------------------------------------
extern "C" void kernel_launch(void* const* d_in, const int* in_sizes, int n_in,
                              void* d_out, int out_size)
{
    const float *x = nullptr, *ipw = nullptr, *cw = nullptr,
                *cb = nullptr, *wb = nullptr, *opw = nullptr;
    for (int i = 0; i < n_in; i++) {
        switch (in_sizes[i]) {
            case M_ * DM_:       x   = (const float*)d_in[i]; break;
            case (DM_ + H_) * DM_: ipw = (const float*)d_in[i]; break;
            case DM_ * 4:        cw  = (const float*)d_in[i]; break;
            case DM_:            cb  = (const float*)d_in[i]; break;
            case H_:             wb  = (const float*)d_in[i]; break;
            case DM_ * DM_:      opw = (const float*)d_in[i]; break;
        }
    }

    static bool attr_done = false;
    if (!attr_done) {
        cudaFuncSetAttribute(hgemm_tc<true>,
                             cudaFuncAttributeMaxDynamicSharedMemorySize, GEMM_SMEM);
        cudaFuncSetAttribute(hgemm_tc<false>,
                             cudaFuncAttributeMaxDynamicSharedMemorySize, GEMM_SMEM);
        cudaFuncSetAttribute(wgemm_kernel,
                             cudaFuncAttributeMaxDynamicSharedMemorySize, WGEMM_SMEM);
        attr_done = true;
    }

    // C0: weight fp32 -> fp16
    f2h_w_kernel<<<1024, 512>>>(ipw, opw);

    // K1b: w-cols fp32 GEMM + x fp16 emit
    wgemm_kernel<<<M_ / 256, 512, WGEMM_SMEM>>>(x, ipw);

    // K1a: xi = x @ in_proj_w[:1024]^T -> fp16 g_xih
    hgemm_tc<true><<<dim3(DM_ / 256, M_ / 128), 512, GEMM_SMEM>>>(nullptr, DM_);

    // K2: per-chunk stats
    chunk_stats_kernel<<<dim3(C_ / 4, H_, B_), dim3(64, 4)>>>(cw, cb, wb);

    // K3: cross-chunk scan
    chunk_scan_kernel<<<dim3(H_, B_), 256>>>();

    // K4: combine -> y (fp16)
    combine_kernel<<<dim3(C_ / 4, H_, B_), dim3(64, 4)>>>(cw, cb, wb);

    // K5: out = y @ out_proj_w^T (fp32 out)
    hgemm_tc<false><<<dim3(DM_ / 256, M_ / 128), 512, GEMM_SMEM>>>(
        (float*)d_out, DM_);
}

// round 12
// speedup vs baseline: 2.0358x; 1.0892x over previous
#include <cuda_runtime.h>
#include <cuda_fp16.h>
#include <cstdint>
#include <cstddef>

// ---------------------------------------------------------------------------
// DecayBlock (Mamba-2 SSD block) — round 12: latency-bound SSD kernels fixed.
//   R11 showed chunk_stats DRAM 13% / issue 25% -> long-scoreboard bound
//   (64 strided loads per thread, MLP~4). Fix: stage the 259x64 fp16 tile
//   through smem with 256 threads x ~8 outstanding uint4 loads (MLP>>),
//   compute from smem. Same arithmetic order -> rel_err unchanged.
// ---------------------------------------------------------------------------

namespace {
constexpr int B_  = 8;
constexpr int S_  = 4096;
constexpr int DM_ = 1024;
constexpr int H_  = 16;
constexpr int N_  = 64;
constexpr int C_  = 64;
constexpr int M_  = B_ * S_;
constexpr int SHH = 72;                    // gemm smem row stride (64 + 8 pad)
constexpr int A_STAGE = 128 * SHH * 2;
constexpr int B_STAGE = 256 * SHH * 2;
constexpr int NSTAGE  = 3;
constexpr int GEMM_SMEM = NSTAGE * (A_STAGE + B_STAGE);   // 165888 B

constexpr int WSTR = 1028;
constexpr int XSTR = 68;
constexpr int WGEMM_SMEM = (16 * WSTR + 256 * XSTR) * 4;  // 135424 B

constexpr int TROWS = 259;   // 256 chunk rows + 3 history rows
constexpr int TPAD  = 72;    // tile col stride in halves (64 + 8)
}

// Scratch (allocation-free: __device__ globals)
__device__ __align__(16) __half g_xih[(size_t)M_ * DM_];   // conv input (fp16)
__device__ __align__(16) float  g_wc[(size_t)M_ * H_];     // w columns (fp32)
__device__ __align__(16) __half g_xh[(size_t)M_ * DM_];    // x fp16
__device__ __align__(16) __half g_yh[(size_t)M_ * DM_];    // y fp16
__device__ __align__(16) __half g_ipwh[(size_t)DM_ * DM_];
__device__ __align__(16) __half g_opwh[(size_t)DM_ * DM_];
__device__ __align__(16) float g_states[B_ * H_ * C_ * N_];
__device__ float g_cnorm[B_ * H_ * C_];
__device__ float g_T[B_ * H_ * C_];
__device__ __align__(16) float g_nstates[B_ * H_ * C_ * N_];
__device__ float g_nnorm[B_ * H_ * C_];

__device__ __forceinline__ uint32_t pk(float lo, float hi) {
    __half2 h = __floats2half2_rn(lo, hi);
    return *reinterpret_cast<uint32_t*>(&h);
}

__device__ __forceinline__ void mma_f16(float* c, const uint32_t* a, const uint32_t* b) {
    asm volatile(
        "mma.sync.aligned.m16n8k16.row.col.f32.f16.f16.f32 "
        "{%0,%1,%2,%3}, {%4,%5,%6,%7}, {%8,%9}, {%0,%1,%2,%3};\n"
        : "+f"(c[0]), "+f"(c[1]), "+f"(c[2]), "+f"(c[3])
        : "r"(a[0]), "r"(a[1]), "r"(a[2]), "r"(a[3]), "r"(b[0]), "r"(b[1]));
}

__device__ __forceinline__ void cp16(uint32_t smem, const void* gmem) {
    asm volatile("cp.async.cg.shared.global [%0], [%1], 16;\n" :: "r"(smem), "l"(gmem));
}

__device__ __forceinline__ void ldsm4(uint32_t* r, uint32_t addr) {
    asm volatile("ldmatrix.sync.aligned.m8n8.x4.shared.b16 {%0,%1,%2,%3}, [%4];"
                 : "=r"(r[0]), "=r"(r[1]), "=r"(r[2]), "=r"(r[3]) : "r"(addr));
}

// Stage a 259x64 fp16 tile (rows s_tile0..s_tile0+258 of batch b, cols
// h*64..h*64+63) into smem with high MLP. 256 threads.
__device__ __forceinline__ void stage_tile(__half (*sx)[TPAD], int b, int s_tile0,
                                           int h, int tid)
{
#pragma unroll
    for (int j = 0; j < 9; j++) {
        const int idx = tid + j * 256;          // 0..2303; need < 2072
        if (idx < TROWS * 8) {
            const int row = idx >> 3;
            const int q   = idx & 7;
            const int s   = s_tile0 + row;
            uint4 v = make_uint4(0, 0, 0, 0);
            if (s >= 0)
                v = *reinterpret_cast<const uint4*>(
                    g_xih + (size_t)(b * S_ + s) * DM_ + h * 64 + q * 8);
            *reinterpret_cast<uint4*>(&sx[row][q * 8]) = v;
        }
    }
}

// ---------------------------------------------------------------------------
// C0: both weight matrices fp32 -> fp16, one launch.
// ---------------------------------------------------------------------------
__global__ __launch_bounds__(512)
void f2h_w_kernel(const float* __restrict__ ipw, const float* __restrict__ opw)
{
    int b = blockIdx.x;
    const float* src;
    __half* dst;
    if (b < 512) { src = ipw; dst = g_ipwh; }
    else         { src = opw; dst = g_opwh; b -= 512; }
    const int i = b * 512 + threadIdx.x;
    float4 v = reinterpret_cast<const float4*>(src)[i];
    reinterpret_cast<uint2*>(dst)[i] = make_uint2(pk(v.x, v.y), pk(v.z, v.w));
}

// ---------------------------------------------------------------------------
// FP16 tensor GEMM (NT): 128x256 block, 512 thr, warp tile 32x64, BK=64,
// 3-stage cp.async, ldmatrix double-buffer. FIRST -> fp16 out to g_xih.
// ---------------------------------------------------------------------------
template <bool FIRST>
__global__ __launch_bounds__(512)
void hgemm_tc(float* __restrict__ Carg, int K)
{
    const __half* A  = FIRST ? g_xh   : g_yh;
    const __half* Bw = FIRST ? g_ipwh : g_opwh;

    extern __shared__ __align__(16) char smem[];
    const uint32_t sbase = (uint32_t)__cvta_generic_to_shared(smem);

    const int tid  = threadIdx.x;
    const int lane = tid & 31;
    const int warp = tid >> 5;
    const int wm   = warp & 3;
    const int wn   = warp >> 2;
    const int grp  = lane >> 2;
    const int tig  = lane & 3;

    const int m0 = blockIdx.y * 128;
    const int n0 = blockIdx.x * 256;

    const int srow = tid >> 2;
    const int sc16 = (tid & 3) * 16;

    const __half* gA  = A  + (size_t)(m0 + srow) * K + sc16;
    const __half* gB0 = Bw + (size_t)(n0 + srow) * K + sc16;
    const __half* gB1 = Bw + (size_t)(n0 + 128 + srow) * K + sc16;

    const uint32_t dAoff  = (uint32_t)(srow * SHH + sc16) * 2;
    const uint32_t dB0off = dAoff;
    const uint32_t dB1off = (uint32_t)((srow + 128) * SHH + sc16) * 2;

    const uint32_t laneA = ((lane & 15) * SHH + (lane >> 4) * 8) * 2;
    const uint32_t laneB = (((lane & 7) + ((lane >> 4) << 3)) * SHH +
                            ((lane >> 3) & 1) * 8) * 2;

    float acc[2][8][4];
#pragma unroll
    for (int i = 0; i < 2; i++)
#pragma unroll
        for (int j = 0; j < 8; j++)
#pragma unroll
            for (int r = 0; r < 4; r++) acc[i][j][r] = 0.f;

    auto aBase = [&](int st) { return sbase + st * A_STAGE; };
    auto bBase = [&](int st) { return sbase + NSTAGE * A_STAGE + st * B_STAGE; };

    auto load_stage = [&](int st, int k0) {
        cp16(aBase(st) + dAoff,       gA  + k0);
        cp16(aBase(st) + dAoff + 16,  gA  + k0 + 8);
        cp16(bBase(st) + dB0off,      gB0 + k0);
        cp16(bBase(st) + dB0off + 16, gB0 + k0 + 8);
        cp16(bBase(st) + dB1off,      gB1 + k0);
        cp16(bBase(st) + dB1off + 16, gB1 + k0 + 8);
    };

    const int NIT = K >> 6;
    load_stage(0, 0);
    asm volatile("cp.async.commit_group;\n" ::: "memory");
    load_stage(1, 64);
    asm volatile("cp.async.commit_group;\n" ::: "memory");

    for (int it = 0; it < NIT; ++it) {
        const int cur = it % NSTAGE;
        if (it < NIT - 1) {
            asm volatile("cp.async.wait_group 1;\n" ::: "memory");
        } else {
            asm volatile("cp.async.wait_group 0;\n" ::: "memory");
        }
        __syncthreads();

        if (it + 2 < NIT) {
            load_stage((it + 2) % NSTAGE, (it + 2) << 6);
            asm volatile("cp.async.commit_group;\n" ::: "memory");
        }

        const uint32_t aSt = aBase(cur);
        const uint32_t bSt = bBase(cur);

        uint32_t afr[2][2][4], bfr[2][4][4];
        auto ldfrag = [&](int buf, int ks) {
#pragma unroll
            for (int mt = 0; mt < 2; mt++)
                ldsm4(afr[buf][mt],
                      aSt + (wm * 32 + mt * 16) * (SHH * 2) + ks * 32 + laneA);
#pragma unroll
            for (int np = 0; np < 4; np++)
                ldsm4(bfr[buf][np],
                      bSt + (wn * 64 + np * 16) * (SHH * 2) + ks * 32 + laneB);
        };
        ldfrag(0, 0);
#pragma unroll
        for (int ks = 0; ks < 4; ks++) {
            const int cb = ks & 1;
            if (ks < 3) ldfrag(cb ^ 1, ks + 1);
#pragma unroll
            for (int mt = 0; mt < 2; mt++)
#pragma unroll
                for (int nt = 0; nt < 8; nt++)
                    mma_f16(acc[mt][nt], afr[cb][mt], &bfr[cb][nt >> 1][(nt & 1) * 2]);
        }
    }
    __syncthreads();

#pragma unroll
    for (int mt = 0; mt < 2; mt++) {
        const int row = m0 + wm * 32 + mt * 16 + grp;
#pragma unroll
        for (int nt = 0; nt < 8; nt++) {
            const int col = n0 + wn * 64 + nt * 8 + tig * 2;
            if (FIRST) {
                *reinterpret_cast<uint32_t*>(
                    &g_xih[(size_t)row * DM_ + col]) = pk(acc[mt][nt][0], acc[mt][nt][1]);
                *reinterpret_cast<uint32_t*>(
                    &g_xih[(size_t)(row + 8) * DM_ + col]) = pk(acc[mt][nt][2], acc[mt][nt][3]);
            } else {
                *reinterpret_cast<float2*>(&Carg[(size_t)row * DM_ + col]) =
                    make_float2(acc[mt][nt][0], acc[mt][nt][1]);
                *reinterpret_cast<float2*>(&Carg[(size_t)(row + 8) * DM_ + col]) =
                    make_float2(acc[mt][nt][2], acc[mt][nt][3]);
            }
        }
    }
}

// ---------------------------------------------------------------------------
// K1b: w-cols fp32 GEMM (dense g_wc out) + fused x fp32->fp16 emit.
// ---------------------------------------------------------------------------
__global__ __launch_bounds__(512)
void wgemm_kernel(const float* __restrict__ x, const float* __restrict__ ipw)
{
    extern __shared__ __align__(16) float fsm[];
    float* Ws = fsm;                 // [16][WSTR]
    float* Xs = fsm + 16 * WSTR;     // [256][XSTR]

    const int tid = threadIdx.x;
    const int cq4 = (tid & 3) * 4;
    const int rg  = tid >> 2;
    const int m0  = blockIdx.x * 256;

    const float4* wsrc = reinterpret_cast<const float4*>(ipw + (size_t)1024 * DM_);
#pragma unroll
    for (int j = 0; j < 8; j++) {
        const int w4 = j * 512 + tid;
        float4 v = wsrc[w4];
        const int r  = w4 >> 8;
        const int cw = (w4 & 255) * 4;
        *reinterpret_cast<float4*>(Ws + r * WSTR + cw) = v;
    }

    float acc[2][4];
#pragma unroll
    for (int r = 0; r < 2; r++)
#pragma unroll
        for (int c = 0; c < 4; c++) acc[r][c] = 0.f;

    const int lrow = tid >> 1;
    const int lk0  = (tid & 1) * 32;

    for (int kc = 0; kc < 16; kc++) {
        const int k0 = kc * 64;
        {
            const float* xsrc = x + (size_t)(m0 + lrow) * DM_ + k0 + lk0;
            __half* xhd = g_xh + (size_t)(m0 + lrow) * DM_ + k0 + lk0;
            float* xdst = Xs + lrow * XSTR + lk0;
#pragma unroll
            for (int q = 0; q < 8; q++) {
                float4 v = *reinterpret_cast<const float4*>(xsrc + q * 4);
                *reinterpret_cast<float4*>(xdst + q * 4) = v;
                *reinterpret_cast<uint2*>(xhd + q * 4) =
                    make_uint2(pk(v.x, v.y), pk(v.z, v.w));
            }
        }
        __syncthreads();

#pragma unroll 4
        for (int k4 = 0; k4 < 16; k4++) {
            float4 xv0 = *reinterpret_cast<const float4*>(Xs + rg * XSTR + k4 * 4);
            float4 xv1 = *reinterpret_cast<const float4*>(Xs + (rg + 128) * XSTR + k4 * 4);
#pragma unroll
            for (int cc = 0; cc < 4; cc++) {
                float4 wv = *reinterpret_cast<const float4*>(
                    Ws + (cq4 + cc) * WSTR + k0 + k4 * 4);
                acc[0][cc] = fmaf(xv0.x, wv.x, acc[0][cc]);
                acc[0][cc] = fmaf(xv0.y, wv.y, acc[0][cc]);
                acc[0][cc] = fmaf(xv0.z, wv.z, acc[0][cc]);
                acc[0][cc] = fmaf(xv0.w, wv.w, acc[0][cc]);
                acc[1][cc] = fmaf(xv1.x, wv.x, acc[1][cc]);
                acc[1][cc] = fmaf(xv1.y, wv.y, acc[1][cc]);
                acc[1][cc] = fmaf(xv1.z, wv.z, acc[1][cc]);
                acc[1][cc] = fmaf(xv1.w, wv.w, acc[1][cc]);
            }
        }
        __syncthreads();
    }

#pragma unroll
    for (int r = 0; r < 2; r++) {
        const int row = m0 + rg + r * 128;
        *reinterpret_cast<float4*>(&g_wc[(size_t)row * H_ + cq4]) =
            make_float4(acc[r][0], acc[r][1], acc[r][2], acc[r][3]);
    }
}

// ---------------------------------------------------------------------------
// K2: per-(b,h) 4-chunk stats — smem-staged tile, rolling conv from smem.
// block (64,4); tile = 259 rows x 64 cols fp16.
// ---------------------------------------------------------------------------
__global__ __launch_bounds__(256)
void chunk_stats_kernel(const float* __restrict__ conv_w,
                        const float* __restrict__ conv_b,
                        const float* __restrict__ w_base)
{
    const int ty = threadIdx.y;
    const int c  = blockIdx.x * 4 + ty;
    const int h  = blockIdx.y, b = blockIdx.z;
    const int n  = threadIdx.x;
    const int tid = ty * 64 + n;

    __shared__ __half sx[TROWS][TPAD];
    __shared__ float sS[4][64];
    __shared__ float sE[4][64];
    __shared__ float sMin[4];

    stage_tile(sx, b, blockIdx.x * 256 - 3, h, tid);

    const int ch = h * 64 + n;
    const float cw0 = conv_w[ch * 4 + 0];
    const float cw1 = conv_w[ch * 4 + 1];
    const float cw2 = conv_w[ch * 4 + 2];
    const float cw3 = conv_w[ch * 4 + 3];
    const float cb  = conv_b[ch];

    const int s0 = c * 64;
    sS[ty][n] = g_wc[(size_t)(b * S_ + s0 + n) * H_ + h] * w_base[h];
    __syncthreads();

    if (n == 0) {
        float run = 0.f, mn = 3.4e38f;
        for (int i = 0; i < 64; i++) {
            run += sS[ty][i];
            sS[ty][i] = run;
            mn = fminf(mn, run);
        }
        sMin[ty] = mn;
    }
    __syncthreads();
    sE[ty][n] = __expf(-sS[ty][n]);
    __syncthreads();

    const int r0 = ty * 64;    // local tile row of (i-3) for i=0
    float xm3 = __half2float(sx[r0 + 0][n]);
    float xm2 = __half2float(sx[r0 + 1][n]);
    float xm1 = __half2float(sx[r0 + 2][n]);

    float r = 0.f, rn = 0.f;
#pragma unroll 8
    for (int i = 0; i < 64; i++) {
        const float x0 = __half2float(sx[r0 + 3 + i][n]);
        const float xv = cb + cw0 * xm3 + cw1 * xm2 + cw2 * xm1 + cw3 * x0;
        xm3 = xm2; xm2 = xm1; xm1 = x0;
        const float e = sE[ty][i];
        r  = fmaf(e, xv, r);
        rn += e;
    }

    const float sc  = __expf(sMin[ty]);
    const int   idx = (b * H_ + h) * C_ + c;
    g_states[idx * N_ + n] = sc * r;
    if (n == 0) {
        g_cnorm[idx] = sc * rn;
        g_T[idx]     = sS[ty][63];
    }
}

// ---------------------------------------------------------------------------
// K3: per-(b,h) cross-chunk scan — 256 threads.
// ---------------------------------------------------------------------------
__global__ __launch_bounds__(256)
void chunk_scan_kernel()
{
    const int h = blockIdx.x, b = blockIdx.y;
    const int tid = threadIdx.x;
    const int n  = tid & 63;
    const int zq = tid >> 6;

    __shared__ float G[65];
    __shared__ float MP[64];
    __shared__ float W[64][64];
    __shared__ float st[64][64];
    __shared__ float cn[64];

    const int base = (b * H_ + h) * C_;

    for (int idx = tid; idx < 4096; idx += 256)
        st[idx >> 6][idx & 63] = g_states[(size_t)base * N_ + idx];
    if (tid < 64) cn[tid] = g_cnorm[base + tid];
    __syncthreads();

    if (tid == 0) {
        float run = 0.f;
        G[0] = 0.f;
        for (int c = 0; c < 64; c++) { run += g_T[base + c]; G[c + 1] = run; }
        float mn = 3.4e38f;
        for (int z = 0; z < 64; z++) { mn = fminf(mn, G[z]); MP[z] = mn; }
    }
    __syncthreads();

    for (int idx = tid; idx < 4096; idx += 256) {
        const int z = idx >> 6, cp = idx & 63;
        W[z][cp] = (cp < z) ? __expf(MP[z] - G[cp + 1]) : 0.f;
    }
    __syncthreads();

    for (int z = zq; z < 64; z += 4) {
        float accv = 0.f;
        for (int cp = 0; cp < z; cp++) accv = fmaf(W[z][cp], st[cp][n], accv);
        g_nstates[(base + z) * N_ + n] = accv;
    }
    if (tid < 64) {
        float accn = 0.f;
        for (int cp = 0; cp < tid; cp++) accn = fmaf(W[tid][cp], cn[cp], accn);
        g_nnorm[base + tid] = accn;
    }
}

// ---------------------------------------------------------------------------
// K4: per-(b,h) 4-chunk combine -> y fp16 — smem-staged tile.
// ---------------------------------------------------------------------------
__global__ __launch_bounds__(256)
void combine_kernel(const float* __restrict__ conv_w,
                    const float* __restrict__ conv_b,
                    const float* __restrict__ w_base)
{
    const int ty = threadIdx.y;
    const int c  = blockIdx.x * 4 + ty;
    const int h  = blockIdx.y, b = blockIdx.z;
    const int n  = threadIdx.x;
    const int tid = ty * 64 + n;

    __shared__ __half sx[TROWS][TPAD];
    __shared__ float sS[4][64];
    __shared__ float sE[4][64], sEMP[4][64], sSDO[4][64];
    __shared__ float sMP[4][64];
    __shared__ float sMax[4];

    stage_tile(sx, b, blockIdx.x * 256 - 3, h, tid);

    const int ch = h * 64 + n;
    const float cw0 = conv_w[ch * 4 + 0];
    const float cw1 = conv_w[ch * 4 + 1];
    const float cw2 = conv_w[ch * 4 + 2];
    const float cw3 = conv_w[ch * 4 + 3];
    const float cb  = conv_b[ch];

    const int s0 = c * 64;
    sS[ty][n] = g_wc[(size_t)(b * S_ + s0 + n) * H_ + h] * w_base[h];
    __syncthreads();

    if (n == 0) {
        float run = 0.f, mn = 3.4e38f, mx = -3.4e38f;
        for (int i = 0; i < 64; i++) {
            run += sS[ty][i];
            sS[ty][i] = run;
            mn = fminf(mn, run);
            sMP[ty][i] = mn;
            mx = fmaxf(mx, run);
        }
        sMax[ty] = mx;
    }
    __syncthreads();
    sE[ty][n]   = __expf(-sS[ty][n]);
    sEMP[ty][n] = __expf(sMP[ty][n]);
    sSDO[ty][n] = __expf(sS[ty][n] - sMax[ty]);
    __syncthreads();

    const int idx = (b * H_ + h) * C_ + c;
    const float ns = g_nstates[idx * N_ + n];
    const float nn = g_nnorm[idx];

    const int r0 = ty * 64;
    float xm3 = __half2float(sx[r0 + 0][n]);
    float xm2 = __half2float(sx[r0 + 1][n]);
    float xm1 = __half2float(sx[r0 + 2][n]);

    float r = 0.f, rn = 0.f;
    __half* yout = g_yh + (size_t)(b * S_ + s0) * DM_ + h * 64 + n;

#pragma unroll 8
    for (int i = 0; i < 64; i++) {
        const float x0 = __half2float(sx[r0 + 3 + i][n]);
        const float xv = cb + cw0 * xm3 + cw1 * xm2 + cw2 * xm1 + cw3 * x0;
        xm3 = xm2; xm2 = xm1; xm1 = x0;
        const float e = sE[ty][i];
        r  = fmaf(e, xv, r);
        rn += e;
        const float emp = sEMP[ty][i];
        const float sdo = sSDO[ty][i];
        const float num = fmaf(sdo, ns, emp * r);
        const float den = fmaf(sdo, nn, emp * rn);
        yout[(size_t)i * DM_] = __float2half_rn(num / den);
    }
}

// ---------------------------------------------------------------------------
// Launch
// ---------------------------------------------------------------------------
extern "C" void kernel_launch(void* const* d_in, const int* in_sizes, int n_in,
                              void* d_out, int out_size)
{
    const float *x = nullptr, *ipw = nullptr, *cw = nullptr,
                *cb = nullptr, *wb = nullptr, *opw = nullptr;
    for (int i = 0; i < n_in; i++) {
        switch (in_sizes[i]) {
            case M_ * DM_:         x   = (const float*)d_in[i]; break;
            case (DM_ + H_) * DM_: ipw = (const float*)d_in[i]; break;
            case DM_ * 4:          cw  = (const float*)d_in[i]; break;
            case DM_:              cb  = (const float*)d_in[i]; break;
            case H_:               wb  = (const float*)d_in[i]; break;
            case DM_ * DM_:        opw = (const float*)d_in[i]; break;
        }
    }

    static bool attr_done = false;
    if (!attr_done) {
        cudaFuncSetAttribute(hgemm_tc<true>,
                             cudaFuncAttributeMaxDynamicSharedMemorySize, GEMM_SMEM);
        cudaFuncSetAttribute(hgemm_tc<false>,
                             cudaFuncAttributeMaxDynamicSharedMemorySize, GEMM_SMEM);
        cudaFuncSetAttribute(wgemm_kernel,
                             cudaFuncAttributeMaxDynamicSharedMemorySize, WGEMM_SMEM);
        attr_done = true;
    }

    // C0: weight fp32 -> fp16
    f2h_w_kernel<<<1024, 512>>>(ipw, opw);

    // K1b: w-cols fp32 GEMM + x fp16 emit
    wgemm_kernel<<<M_ / 256, 512, WGEMM_SMEM>>>(x, ipw);

    // K1a: xi -> fp16 g_xih
    hgemm_tc<true><<<dim3(DM_ / 256, M_ / 128), 512, GEMM_SMEM>>>(nullptr, DM_);

    // K2: per-chunk stats (smem-staged)
    chunk_stats_kernel<<<dim3(C_ / 4, H_, B_), dim3(64, 4)>>>(cw, cb, wb);

    // K3: cross-chunk scan
    chunk_scan_kernel<<<dim3(H_, B_), 256>>>();

    // K4: combine -> y fp16 (smem-staged)
    combine_kernel<<<dim3(C_ / 4, H_, B_), dim3(64, 4)>>>(cw, cb, wb);

    // K5: out = y @ out_proj_w^T (fp32 out)
    hgemm_tc<false><<<dim3(DM_ / 256, M_ / 128), 512, GEMM_SMEM>>>(
        (float*)d_out, DM_);
}